// round 5
// baseline (speedup 1.0000x reference)
#include <cuda_runtime.h>

#define LDIM 128
#define NMAX 50000
#define EMAX 800000
#define SCAN_THREADS 1024

// Scratch (allocation-free rule: __device__ globals)
__device__ __align__(16) float g_xws[(size_t)NMAX * LDIM]; // (x@W)*dinv[row]
__device__ int g_cnt[NMAX];      // in-degree (excl. self loop)
__device__ int g_off[NMAX];      // CSR offsets (exclusive scan of cnt)
__device__ int g_cur[NMAX];      // fill cursors (init = g_off)
__device__ int g_adj[EMAX];      // src indices bucketed by dst

// ---------------------------------------------------------------------------
// K0: zero counters
// ---------------------------------------------------------------------------
__global__ void zero_kernel(int N) {
    int i = blockIdx.x * blockDim.x + threadIdx.x;
    if (i < N) g_cnt[i] = 0;
}

// ---------------------------------------------------------------------------
// K1: histogram of dst
// ---------------------------------------------------------------------------
__global__ void hist_kernel(const int* __restrict__ dst, int E) {
    int e = blockIdx.x * blockDim.x + threadIdx.x;
    if (e < E) atomicAdd(&g_cnt[dst[e]], 1);
}

// ---------------------------------------------------------------------------
// K2: single-block exclusive scan of g_cnt -> g_off, and g_cur = g_off.
// ---------------------------------------------------------------------------
__global__ __launch_bounds__(SCAN_THREADS) void scan_kernel(int N) {
    __shared__ int warpsum[32];
    const int C = (N + SCAN_THREADS - 1) / SCAN_THREADS;
    int t = threadIdx.x, lane = t & 31, wid = t >> 5;
    int begin = t * C;
    int end = min(begin + C, N);

    int sum = 0;
    for (int i = begin; i < end; i++) sum += g_cnt[i];

    int x = sum;
    #pragma unroll
    for (int off = 1; off < 32; off <<= 1) {
        int y = __shfl_up_sync(0xFFFFFFFFu, x, off);
        if (lane >= off) x += y;
    }
    if (lane == 31) warpsum[wid] = x;
    __syncthreads();
    if (wid == 0) {
        int w = warpsum[lane];
        #pragma unroll
        for (int off = 1; off < 32; off <<= 1) {
            int y = __shfl_up_sync(0xFFFFFFFFu, w, off);
            if (lane >= off) w += y;
        }
        warpsum[lane] = w;
    }
    __syncthreads();
    int prefix = ((wid == 0) ? 0 : warpsum[wid - 1]) + x - sum;

    int run = prefix;
    for (int i = begin; i < end; i++) {
        int c = g_cnt[i];
        g_off[i] = run;
        g_cur[i] = run;
        run += c;
    }
}

// ---------------------------------------------------------------------------
// K3: bucket fill: adj[cur[d]++] = src  (cur pre-seeded with offsets)
// ---------------------------------------------------------------------------
__global__ void fill_kernel(const int* __restrict__ src,
                            const int* __restrict__ dst, int E) {
    int e = blockIdx.x * blockDim.x + threadIdx.x;
    if (e >= E) return;
    int d = dst[e];
    int pos = atomicAdd(&g_cur[d], 1);
    g_adj[pos] = src[e];
}

// ---------------------------------------------------------------------------
// K4: xws[row] = (x[row] @ W) * rsqrt(cnt[row]+1)
// 64 rows x 128 cols per block, 256 threads, each thread 4 rows x 8 cols.
// ---------------------------------------------------------------------------
__global__ __launch_bounds__(256) void gemm_scale_kernel(
    const float* __restrict__ x, const float* __restrict__ W, int N)
{
    extern __shared__ float smem[];
    float* Ws = smem;                  // [128][128]
    float* xs = smem + LDIM * LDIM;    // [64][128]

    const int t = threadIdx.x;
    const int block_row = blockIdx.x * 64;

    #pragma unroll
    for (int i = t; i < LDIM * LDIM / 4; i += 256)
        ((float4*)Ws)[i] = ((const float4*)W)[i];

    for (int i = t; i < 64 * LDIM / 4; i += 256) {
        int r = i >> 5;
        int c4 = i & 31;
        int row = block_row + r;
        float4 v = make_float4(0.f, 0.f, 0.f, 0.f);
        if (row < N) v = ((const float4*)x)[(size_t)row * (LDIM / 4) + c4];
        ((float4*)xs)[i] = v;
    }
    __syncthreads();

    const int tx = t & 15;
    const int ty = t >> 4;
    const int r0 = ty * 4;
    const int c0 = tx * 8;

    float acc[4][8];
    #pragma unroll
    for (int i = 0; i < 4; i++)
        #pragma unroll
        for (int j = 0; j < 8; j++) acc[i][j] = 0.0f;

    #pragma unroll 4
    for (int k4 = 0; k4 < LDIM / 4; k4++) {
        float4 a4[4];
        #pragma unroll
        for (int i = 0; i < 4; i++)
            a4[i] = *(const float4*)&xs[(r0 + i) * LDIM + k4 * 4];

        #pragma unroll
        for (int kk = 0; kk < 4; kk++) {
            int k = k4 * 4 + kk;
            float4 b0 = *(const float4*)&Ws[k * LDIM + c0];
            float4 b1 = *(const float4*)&Ws[k * LDIM + c0 + 4];
            float bv[8] = {b0.x, b0.y, b0.z, b0.w, b1.x, b1.y, b1.z, b1.w};
            #pragma unroll
            for (int i = 0; i < 4; i++) {
                float av = ((const float*)&a4[i])[kk];
                #pragma unroll
                for (int j = 0; j < 8; j++)
                    acc[i][j] = fmaf(av, bv[j], acc[i][j]);
            }
        }
    }

    #pragma unroll
    for (int i = 0; i < 4; i++) {
        int row = block_row + r0 + i;
        if (row < N) {
            float dinv = rsqrtf((float)(g_cnt[row] + 1));
            float4 o0, o1;
            o0.x = acc[i][0] * dinv; o0.y = acc[i][1] * dinv;
            o0.z = acc[i][2] * dinv; o0.w = acc[i][3] * dinv;
            o1.x = acc[i][4] * dinv; o1.y = acc[i][5] * dinv;
            o1.z = acc[i][6] * dinv; o1.w = acc[i][7] * dinv;
            float* op = &g_xws[(size_t)row * LDIM + c0];
            *(float4*)op = o0;
            *(float4*)(op + 4) = o1;
        }
    }
}

// ---------------------------------------------------------------------------
// K5: one warp per node: reg-accumulate neighbors, fuse finalize + softmax.
// ---------------------------------------------------------------------------
__global__ void gather_finalize_kernel(const float* __restrict__ b,
                                       float* __restrict__ out, int N)
{
    int gw = (blockIdx.x * blockDim.x + threadIdx.x) >> 5;
    int lane = threadIdx.x & 31;
    if (gw >= N) return;

    int start = g_off[gw];
    int len   = g_cnt[gw];
    const size_t lbase = (size_t)lane * 4;

    float4 acc = make_float4(0.f, 0.f, 0.f, 0.f);

    for (int base = 0; base < len; base += 32) {
        int idx = 0;
        if (base + lane < len) idx = __ldg(&g_adj[start + base + lane]);
        int m = min(32, len - base);
        int j = 0;
        for (; j + 8 <= m; j += 8) {
            int s0 = __shfl_sync(0xFFFFFFFFu, idx, j + 0);
            int s1 = __shfl_sync(0xFFFFFFFFu, idx, j + 1);
            int s2 = __shfl_sync(0xFFFFFFFFu, idx, j + 2);
            int s3 = __shfl_sync(0xFFFFFFFFu, idx, j + 3);
            int s4 = __shfl_sync(0xFFFFFFFFu, idx, j + 4);
            int s5 = __shfl_sync(0xFFFFFFFFu, idx, j + 5);
            int s6 = __shfl_sync(0xFFFFFFFFu, idx, j + 6);
            int s7 = __shfl_sync(0xFFFFFFFFu, idx, j + 7);
            float4 v0 = *(const float4*)&g_xws[(size_t)s0 * LDIM + lbase];
            float4 v1 = *(const float4*)&g_xws[(size_t)s1 * LDIM + lbase];
            float4 v2 = *(const float4*)&g_xws[(size_t)s2 * LDIM + lbase];
            float4 v3 = *(const float4*)&g_xws[(size_t)s3 * LDIM + lbase];
            float4 v4 = *(const float4*)&g_xws[(size_t)s4 * LDIM + lbase];
            float4 v5 = *(const float4*)&g_xws[(size_t)s5 * LDIM + lbase];
            float4 v6 = *(const float4*)&g_xws[(size_t)s6 * LDIM + lbase];
            float4 v7 = *(const float4*)&g_xws[(size_t)s7 * LDIM + lbase];
            acc.x += v0.x + v1.x + v2.x + v3.x + v4.x + v5.x + v6.x + v7.x;
            acc.y += v0.y + v1.y + v2.y + v3.y + v4.y + v5.y + v6.y + v7.y;
            acc.z += v0.z + v1.z + v2.z + v3.z + v4.z + v5.z + v6.z + v7.z;
            acc.w += v0.w + v1.w + v2.w + v3.w + v4.w + v5.w + v6.w + v7.w;
        }
        for (; j < m; j++) {
            int s = __shfl_sync(0xFFFFFFFFu, idx, j);
            float4 v = *(const float4*)&g_xws[(size_t)s * LDIM + lbase];
            acc.x += v.x; acc.y += v.y; acc.z += v.z; acc.w += v.w;
        }
    }

    float4 w  = *(const float4*)&g_xws[(size_t)gw * LDIM + lbase];
    float4 bb = *(const float4*)&b[lbase];
    float dinv = rsqrtf((float)(len + 1));

    float v0 = fmaxf(fmaf(dinv, acc.x + w.x, bb.x), 0.0f);
    float v1 = fmaxf(fmaf(dinv, acc.y + w.y, bb.y), 0.0f);
    float v2 = fmaxf(fmaf(dinv, acc.z + w.z, bb.z), 0.0f);
    float v3 = fmaxf(fmaf(dinv, acc.w + w.w, bb.w), 0.0f);

    float m = fmaxf(fmaxf(v0, v1), fmaxf(v2, v3));
    #pragma unroll
    for (int off = 16; off > 0; off >>= 1)
        m = fmaxf(m, __shfl_xor_sync(0xFFFFFFFFu, m, off));

    float e0 = __expf(v0 - m);
    float e1 = __expf(v1 - m);
    float e2 = __expf(v2 - m);
    float e3 = __expf(v3 - m);
    float s = e0 + e1 + e2 + e3;
    #pragma unroll
    for (int off = 16; off > 0; off >>= 1)
        s += __shfl_xor_sync(0xFFFFFFFFu, s, off);

    float inv = __frcp_rn(s);
    float4 o;
    o.x = e0 * inv; o.y = e1 * inv; o.z = e2 * inv; o.w = e3 * inv;
    *(float4*)&out[(size_t)gw * LDIM + lbase] = o;
}

// ---------------------------------------------------------------------------
extern "C" void kernel_launch(void* const* d_in, const int* in_sizes, int n_in,
                              void* d_out, int out_size)
{
    const float* x  = (const float*)d_in[0];
    const int*   ei = (const int*)d_in[1];
    const float* W  = (const float*)d_in[2];
    const float* b  = (const float*)d_in[3];
    float* out = (float*)d_out;

    int N = in_sizes[0] / LDIM;   // 50000
    int E = in_sizes[1] / 2;      // 800000
    const int* src = ei;
    const int* dst = ei + E;

    zero_kernel<<<(N + 255) / 256, 256>>>(N);
    hist_kernel<<<(E + 255) / 256, 256>>>(dst, E);
    scan_kernel<<<1, SCAN_THREADS>>>(N);
    fill_kernel<<<(E + 255) / 256, 256>>>(src, dst, E);

    cudaFuncSetAttribute(gemm_scale_kernel,
                         cudaFuncAttributeMaxDynamicSharedMemorySize, 96 * 1024);
    gemm_scale_kernel<<<(N + 63) / 64, 256, 96 * 1024>>>(x, W, N);

    long long gthreads = (long long)N * 32;
    gather_finalize_kernel<<<(int)((gthreads + 255) / 256), 256>>>(b, out, N);
}

// round 7
// speedup vs baseline: 1.0114x; 1.0114x over previous
#include <cuda_runtime.h>

#define LDIM 128
#define NMAX 50000
#define EMAX 800000
#define SCAN_THREADS 1024

// Scratch (allocation-free rule: __device__ globals)
__device__ __align__(16) float g_xws[(size_t)NMAX * LDIM]; // (x@W)*dinv[row]
__device__ int g_cnt[NMAX];      // in-degree (excl. self loop)
__device__ int g_off[NMAX];      // CSR offsets
__device__ int g_cur[NMAX];      // fill cursors (init = g_off)
__device__ int g_adj[EMAX];      // src indices bucketed by dst

// ---------------------------------------------------------------------------
// K0-K3: CSR build
// ---------------------------------------------------------------------------
__global__ void zero_kernel(int N) {
    int i = blockIdx.x * blockDim.x + threadIdx.x;
    if (i < N) g_cnt[i] = 0;
}

__global__ void hist_kernel(const int* __restrict__ dst, int E) {
    int e = blockIdx.x * blockDim.x + threadIdx.x;
    if (e < E) atomicAdd(&g_cnt[dst[e]], 1);
}

__global__ __launch_bounds__(SCAN_THREADS) void scan_kernel(int N) {
    __shared__ int warpsum[32];
    const int C = (N + SCAN_THREADS - 1) / SCAN_THREADS;
    int t = threadIdx.x, lane = t & 31, wid = t >> 5;
    int begin = t * C;
    int end = min(begin + C, N);

    int sum = 0;
    for (int i = begin; i < end; i++) sum += g_cnt[i];

    int x = sum;
    #pragma unroll
    for (int off = 1; off < 32; off <<= 1) {
        int y = __shfl_up_sync(0xFFFFFFFFu, x, off);
        if (lane >= off) x += y;
    }
    if (lane == 31) warpsum[wid] = x;
    __syncthreads();
    if (wid == 0) {
        int w = warpsum[lane];
        #pragma unroll
        for (int off = 1; off < 32; off <<= 1) {
            int y = __shfl_up_sync(0xFFFFFFFFu, w, off);
            if (lane >= off) w += y;
        }
        warpsum[lane] = w;
    }
    __syncthreads();
    int prefix = ((wid == 0) ? 0 : warpsum[wid - 1]) + x - sum;

    int run = prefix;
    for (int i = begin; i < end; i++) {
        int c = g_cnt[i];
        g_off[i] = run;
        g_cur[i] = run;
        run += c;
    }
}

__global__ void fill_kernel(const int* __restrict__ src,
                            const int* __restrict__ dst, int E) {
    int e = blockIdx.x * blockDim.x + threadIdx.x;
    if (e >= E) return;
    int d = dst[e];
    int pos = atomicAdd(&g_cur[d], 1);
    g_adj[pos] = src[e];
}

// ---------------------------------------------------------------------------
// K4: tensor-core GEMM via mma.sync m16n8k8 tf32, 3xTF32 compensation.
// CTA: 128 rows x 128 cols, 8 warps (16 rows each). K staged in 2 halves of 64.
// Smem pads: A stride 68 (4r+c bank map), B stride 136 (8r+n) -> conflict-free.
// ---------------------------------------------------------------------------
#define A_STRIDE 68
#define B_STRIDE 136
#define OFF_AH 0
#define OFF_AL (128 * A_STRIDE)
#define OFF_BH (2 * 128 * A_STRIDE)
#define OFF_BL (2 * 128 * A_STRIDE + 64 * B_STRIDE)
#define GEMM_SMEM ((2 * 128 * A_STRIDE + 2 * 64 * B_STRIDE) * 4)

__device__ __forceinline__ unsigned tf32_rna(float v) {
    unsigned h;
    asm("cvt.rna.tf32.f32 %0, %1;" : "=r"(h) : "f"(v));
    return h;
}

__device__ __forceinline__ void mma_tf32(float* c,
                                         unsigned a0, unsigned a1,
                                         unsigned a2, unsigned a3,
                                         unsigned b0, unsigned b1) {
    asm volatile(
        "mma.sync.aligned.m16n8k8.row.col.f32.tf32.tf32.f32 "
        "{%0,%1,%2,%3}, {%4,%5,%6,%7}, {%8,%9}, {%0,%1,%2,%3};"
        : "+f"(c[0]), "+f"(c[1]), "+f"(c[2]), "+f"(c[3])
        : "r"(a0), "r"(a1), "r"(a2), "r"(a3), "r"(b0), "r"(b1));
}

__global__ __launch_bounds__(256) void gemm_mma_kernel(
    const float* __restrict__ x, const float* __restrict__ W, int N)
{
    extern __shared__ unsigned smu[];
    const int tid = threadIdx.x;
    const int wid = tid >> 5;
    const int lane = tid & 31;
    const int g = lane >> 2;      // groupID 0..7
    const int t4 = lane & 3;      // threadID_in_group 0..3
    const int block_row = blockIdx.x * 128;
    const int wr0 = wid * 16;     // warp's row block within tile

    float acc[16][4];
    #pragma unroll
    for (int nt = 0; nt < 16; nt++)
        #pragma unroll
        for (int j = 0; j < 4; j++) acc[nt][j] = 0.0f;

    #pragma unroll 1
    for (int stage = 0; stage < 2; stage++) {
        int k0 = stage * 64;
        if (stage) __syncthreads();   // protect smem reuse

        // stage A: 128 rows x 64 cols (hi/lo split)
        for (int i = tid; i < 128 * 64; i += 256) {
            int r = i >> 6, c = i & 63;
            int grow = block_row + r;
            float v = (grow < N) ? __ldg(&x[(size_t)grow * LDIM + k0 + c]) : 0.0f;
            unsigned hb = tf32_rna(v);
            unsigned lb = tf32_rna(v - __uint_as_float(hb));
            smu[OFF_AH + r * A_STRIDE + c] = hb;
            smu[OFF_AL + r * A_STRIDE + c] = lb;
        }
        // stage B = W rows k0..k0+63, all 128 cols (col-major frag reads later)
        for (int i = tid; i < 64 * 128; i += 256) {
            int r = i >> 7, c = i & 127;
            float v = __ldg(&W[(size_t)(k0 + r) * LDIM + c]);
            unsigned hb = tf32_rna(v);
            unsigned lb = tf32_rna(v - __uint_as_float(hb));
            smu[OFF_BH + r * B_STRIDE + c] = hb;
            smu[OFF_BL + r * B_STRIDE + c] = lb;
        }
        __syncthreads();

        #pragma unroll
        for (int ks = 0; ks < 8; ks++) {
            int kk = ks * 8;
            const unsigned* Ah = smu + OFF_AH + (wr0 + g) * A_STRIDE + kk + t4;
            const unsigned* Al = smu + OFF_AL + (wr0 + g) * A_STRIDE + kk + t4;
            unsigned ah0 = Ah[0];
            unsigned ah1 = Ah[8 * A_STRIDE];
            unsigned ah2 = Ah[4];
            unsigned ah3 = Ah[8 * A_STRIDE + 4];
            unsigned al0 = Al[0];
            unsigned al1 = Al[8 * A_STRIDE];
            unsigned al2 = Al[4];
            unsigned al3 = Al[8 * A_STRIDE + 4];

            const unsigned* Bh = smu + OFF_BH + (kk + t4) * B_STRIDE + g;
            const unsigned* Bl = smu + OFF_BL + (kk + t4) * B_STRIDE + g;
            #pragma unroll
            for (int nt = 0; nt < 16; nt++) {
                unsigned bh0 = Bh[nt * 8];
                unsigned bh1 = Bh[4 * B_STRIDE + nt * 8];
                unsigned bl0 = Bl[nt * 8];
                unsigned bl1 = Bl[4 * B_STRIDE + nt * 8];
                mma_tf32(acc[nt], ah0, ah1, ah2, ah3, bh0, bh1);
                mma_tf32(acc[nt], ah0, ah1, ah2, ah3, bl0, bl1);
                mma_tf32(acc[nt], al0, al1, al2, al3, bh0, bh1);
            }
        }
    }

    // epilogue: c0/c1 -> row g, cols 2*t4,2*t4+1 ; c2/c3 -> row g+8
    int row0 = block_row + wr0 + g;
    int row1 = row0 + 8;
    float dinv0 = (row0 < N) ? rsqrtf((float)(g_cnt[row0] + 1)) : 0.0f;
    float dinv1 = (row1 < N) ? rsqrtf((float)(g_cnt[row1] + 1)) : 0.0f;

    #pragma unroll
    for (int nt = 0; nt < 16; nt++) {
        int col = nt * 8 + 2 * t4;
        if (row0 < N) {
            float2 o = make_float2(acc[nt][0] * dinv0, acc[nt][1] * dinv0);
            *(float2*)&g_xws[(size_t)row0 * LDIM + col] = o;
        }
        if (row1 < N) {
            float2 o = make_float2(acc[nt][2] * dinv1, acc[nt][3] * dinv1);
            *(float2*)&g_xws[(size_t)row1 * LDIM + col] = o;
        }
    }
}

// ---------------------------------------------------------------------------
// K5: one warp per node: reg-accumulate neighbors, fused finalize + softmax.
// ---------------------------------------------------------------------------
__global__ void gather_finalize_kernel(const float* __restrict__ b,
                                       float* __restrict__ out, int N)
{
    int gw = (blockIdx.x * blockDim.x + threadIdx.x) >> 5;
    int lane = threadIdx.x & 31;
    if (gw >= N) return;

    int start = g_off[gw];
    int len   = g_cnt[gw];
    const size_t lbase = (size_t)lane * 4;

    float4 acc = make_float4(0.f, 0.f, 0.f, 0.f);

    for (int base = 0; base < len; base += 32) {
        int idx = 0;
        if (base + lane < len) idx = __ldg(&g_adj[start + base + lane]);
        int m = min(32, len - base);
        int j = 0;
        for (; j + 8 <= m; j += 8) {
            int s0 = __shfl_sync(0xFFFFFFFFu, idx, j + 0);
            int s1 = __shfl_sync(0xFFFFFFFFu, idx, j + 1);
            int s2 = __shfl_sync(0xFFFFFFFFu, idx, j + 2);
            int s3 = __shfl_sync(0xFFFFFFFFu, idx, j + 3);
            int s4 = __shfl_sync(0xFFFFFFFFu, idx, j + 4);
            int s5 = __shfl_sync(0xFFFFFFFFu, idx, j + 5);
            int s6 = __shfl_sync(0xFFFFFFFFu, idx, j + 6);
            int s7 = __shfl_sync(0xFFFFFFFFu, idx, j + 7);
            float4 v0 = *(const float4*)&g_xws[(size_t)s0 * LDIM + lbase];
            float4 v1 = *(const float4*)&g_xws[(size_t)s1 * LDIM + lbase];
            float4 v2 = *(const float4*)&g_xws[(size_t)s2 * LDIM + lbase];
            float4 v3 = *(const float4*)&g_xws[(size_t)s3 * LDIM + lbase];
            float4 v4 = *(const float4*)&g_xws[(size_t)s4 * LDIM + lbase];
            float4 v5 = *(const float4*)&g_xws[(size_t)s5 * LDIM + lbase];
            float4 v6 = *(const float4*)&g_xws[(size_t)s6 * LDIM + lbase];
            float4 v7 = *(const float4*)&g_xws[(size_t)s7 * LDIM + lbase];
            acc.x += v0.x + v1.x + v2.x + v3.x + v4.x + v5.x + v6.x + v7.x;
            acc.y += v0.y + v1.y + v2.y + v3.y + v4.y + v5.y + v6.y + v7.y;
            acc.z += v0.z + v1.z + v2.z + v3.z + v4.z + v5.z + v6.z + v7.z;
            acc.w += v0.w + v1.w + v2.w + v3.w + v4.w + v5.w + v6.w + v7.w;
        }
        for (; j < m; j++) {
            int s = __shfl_sync(0xFFFFFFFFu, idx, j);
            float4 v = *(const float4*)&g_xws[(size_t)s * LDIM + lbase];
            acc.x += v.x; acc.y += v.y; acc.z += v.z; acc.w += v.w;
        }
    }

    float4 w  = *(const float4*)&g_xws[(size_t)gw * LDIM + lbase];
    float4 bb = *(const float4*)&b[lbase];
    float dinv = rsqrtf((float)(len + 1));

    float v0 = fmaxf(fmaf(dinv, acc.x + w.x, bb.x), 0.0f);
    float v1 = fmaxf(fmaf(dinv, acc.y + w.y, bb.y), 0.0f);
    float v2 = fmaxf(fmaf(dinv, acc.z + w.z, bb.z), 0.0f);
    float v3 = fmaxf(fmaf(dinv, acc.w + w.w, bb.w), 0.0f);

    float m = fmaxf(fmaxf(v0, v1), fmaxf(v2, v3));
    #pragma unroll
    for (int off = 16; off > 0; off >>= 1)
        m = fmaxf(m, __shfl_xor_sync(0xFFFFFFFFu, m, off));

    float e0 = __expf(v0 - m);
    float e1 = __expf(v1 - m);
    float e2 = __expf(v2 - m);
    float e3 = __expf(v3 - m);
    float s = e0 + e1 + e2 + e3;
    #pragma unroll
    for (int off = 16; off > 0; off >>= 1)
        s += __shfl_xor_sync(0xFFFFFFFFu, s, off);

    float inv = __frcp_rn(s);
    float4 o;
    o.x = e0 * inv; o.y = e1 * inv; o.z = e2 * inv; o.w = e3 * inv;
    *(float4*)&out[(size_t)gw * LDIM + lbase] = o;
}

// ---------------------------------------------------------------------------
extern "C" void kernel_launch(void* const* d_in, const int* in_sizes, int n_in,
                              void* d_out, int out_size)
{
    const float* x  = (const float*)d_in[0];
    const int*   ei = (const int*)d_in[1];
    const float* W  = (const float*)d_in[2];
    const float* b  = (const float*)d_in[3];
    float* out = (float*)d_out;

    int N = in_sizes[0] / LDIM;   // 50000
    int E = in_sizes[1] / 2;      // 800000
    const int* src = ei;
    const int* dst = ei + E;

    zero_kernel<<<(N + 255) / 256, 256>>>(N);
    hist_kernel<<<(E + 255) / 256, 256>>>(dst, E);
    scan_kernel<<<1, SCAN_THREADS>>>(N);
    fill_kernel<<<(E + 255) / 256, 256>>>(src, dst, E);

    cudaFuncSetAttribute(gemm_mma_kernel,
                         cudaFuncAttributeMaxDynamicSharedMemorySize, GEMM_SMEM);
    gemm_mma_kernel<<<(N + 127) / 128, 256, GEMM_SMEM>>>(x, W, N);

    long long gthreads = (long long)N * 32;
    gather_finalize_kernel<<<(int)((gthreads + 255) / 256), 256>>>(b, out, N);
}

// round 8
// speedup vs baseline: 1.5336x; 1.5164x over previous
#include <cuda_runtime.h>

#define LDIM 128
#define NMAX 50000
#define EMAX 800000
#define SCAN_BLK 1024
#define NCHUNK_MAX ((NMAX + SCAN_BLK - 1) / SCAN_BLK)

// Scratch (allocation-free rule: __device__ globals)
__device__ __align__(16) float g_xws[(size_t)NMAX * LDIM]; // (x@W)*dinv[row]
__device__ int g_cnt[NMAX];      // in-degree (excl. self loop)
__device__ int g_off[NMAX];      // CSR offsets
__device__ int g_cur[NMAX];      // fill cursors (init = g_off)
__device__ int g_adj[EMAX];      // src indices bucketed by dst
__device__ int g_part[NCHUNK_MAX];

// ---------------------------------------------------------------------------
// K0: zero counters
// ---------------------------------------------------------------------------
__global__ void zero_kernel(int N) {
    int i = blockIdx.x * blockDim.x + threadIdx.x;
    if (i < N) g_cnt[i] = 0;
}

// ---------------------------------------------------------------------------
// K1: histogram of dst
// ---------------------------------------------------------------------------
__global__ void hist_kernel(const int* __restrict__ dst, int E) {
    int e = blockIdx.x * blockDim.x + threadIdx.x;
    if (e < E) atomicAdd(&g_cnt[dst[e]], 1);
}

// ---------------------------------------------------------------------------
// K2a: per-chunk exclusive scan (coalesced, 1024/block), emit chunk totals
// ---------------------------------------------------------------------------
__global__ __launch_bounds__(SCAN_BLK) void scan1_kernel(int N) {
    __shared__ int warpsum[32];
    int t = threadIdx.x, lane = t & 31, wid = t >> 5;
    int gid = blockIdx.x * SCAN_BLK + t;
    int v = (gid < N) ? g_cnt[gid] : 0;

    int x = v;
    #pragma unroll
    for (int off = 1; off < 32; off <<= 1) {
        int y = __shfl_up_sync(0xFFFFFFFFu, x, off);
        if (lane >= off) x += y;
    }
    if (lane == 31) warpsum[wid] = x;
    __syncthreads();
    if (wid == 0) {
        int w = warpsum[lane];
        #pragma unroll
        for (int off = 1; off < 32; off <<= 1) {
            int y = __shfl_up_sync(0xFFFFFFFFu, w, off);
            if (lane >= off) w += y;
        }
        warpsum[lane] = w;
    }
    __syncthreads();
    int warp_prefix = (wid == 0) ? 0 : warpsum[wid - 1];
    if (gid < N) g_off[gid] = warp_prefix + x - v;
    if (t == SCAN_BLK - 1) g_part[blockIdx.x] = warp_prefix + x;
}

// ---------------------------------------------------------------------------
// K2b: single-warp shfl scan over chunk totals (nchunk <= 64)
// ---------------------------------------------------------------------------
__global__ void scan2_kernel(int nchunk) {
    int lane = threadIdx.x;
    int running = 0;
    for (int base = 0; base < nchunk; base += 32) {
        int idx = base + lane;
        int v = (idx < nchunk) ? g_part[idx] : 0;
        int x = v;
        #pragma unroll
        for (int off = 1; off < 32; off <<= 1) {
            int y = __shfl_up_sync(0xFFFFFFFFu, x, off);
            if (lane >= off) x += y;
        }
        if (idx < nchunk) g_part[idx] = running + x - v;
        running += __shfl_sync(0xFFFFFFFFu, x, 31);
    }
}

// ---------------------------------------------------------------------------
// K2c: add chunk offsets back; seed cursors
// ---------------------------------------------------------------------------
__global__ __launch_bounds__(SCAN_BLK) void scan3_kernel(int N) {
    int gid = blockIdx.x * SCAN_BLK + threadIdx.x;
    if (gid < N) {
        int o = g_off[gid] + g_part[blockIdx.x];
        g_off[gid] = o;
        g_cur[gid] = o;
    }
}

// ---------------------------------------------------------------------------
// K3: bucket fill: adj[cur[d]++] = src
// ---------------------------------------------------------------------------
__global__ void fill_kernel(const int* __restrict__ src,
                            const int* __restrict__ dst, int E) {
    int e = blockIdx.x * blockDim.x + threadIdx.x;
    if (e >= E) return;
    int d = dst[e];
    int pos = atomicAdd(&g_cur[d], 1);
    g_adj[pos] = src[e];
}

// ---------------------------------------------------------------------------
// K4: tensor-core GEMM via mma.sync m16n8k8 tf32, 3xTF32 compensation.
// ---------------------------------------------------------------------------
#define A_STRIDE 68
#define B_STRIDE 136
#define OFF_AH 0
#define OFF_AL (128 * A_STRIDE)
#define OFF_BH (2 * 128 * A_STRIDE)
#define OFF_BL (2 * 128 * A_STRIDE + 64 * B_STRIDE)
#define GEMM_SMEM ((2 * 128 * A_STRIDE + 2 * 64 * B_STRIDE) * 4)

__device__ __forceinline__ unsigned tf32_rna(float v) {
    unsigned h;
    asm("cvt.rna.tf32.f32 %0, %1;" : "=r"(h) : "f"(v));
    return h;
}

__device__ __forceinline__ void mma_tf32(float* c,
                                         unsigned a0, unsigned a1,
                                         unsigned a2, unsigned a3,
                                         unsigned b0, unsigned b1) {
    asm volatile(
        "mma.sync.aligned.m16n8k8.row.col.f32.tf32.tf32.f32 "
        "{%0,%1,%2,%3}, {%4,%5,%6,%7}, {%8,%9}, {%0,%1,%2,%3};"
        : "+f"(c[0]), "+f"(c[1]), "+f"(c[2]), "+f"(c[3])
        : "r"(a0), "r"(a1), "r"(a2), "r"(a3), "r"(b0), "r"(b1));
}

__global__ __launch_bounds__(256) void gemm_mma_kernel(
    const float* __restrict__ x, const float* __restrict__ W, int N)
{
    extern __shared__ unsigned smu[];
    const int tid = threadIdx.x;
    const int wid = tid >> 5;
    const int lane = tid & 31;
    const int g = lane >> 2;
    const int t4 = lane & 3;
    const int block_row = blockIdx.x * 128;
    const int wr0 = wid * 16;

    float acc[16][4];
    #pragma unroll
    for (int nt = 0; nt < 16; nt++)
        #pragma unroll
        for (int j = 0; j < 4; j++) acc[nt][j] = 0.0f;

    #pragma unroll 1
    for (int stage = 0; stage < 2; stage++) {
        int k0 = stage * 64;
        if (stage) __syncthreads();

        for (int i = tid; i < 128 * 64; i += 256) {
            int r = i >> 6, c = i & 63;
            int grow = block_row + r;
            float v = (grow < N) ? __ldg(&x[(size_t)grow * LDIM + k0 + c]) : 0.0f;
            unsigned hb = tf32_rna(v);
            unsigned lb = tf32_rna(v - __uint_as_float(hb));
            smu[OFF_AH + r * A_STRIDE + c] = hb;
            smu[OFF_AL + r * A_STRIDE + c] = lb;
        }
        for (int i = tid; i < 64 * 128; i += 256) {
            int r = i >> 7, c = i & 127;
            float v = __ldg(&W[(size_t)(k0 + r) * LDIM + c]);
            unsigned hb = tf32_rna(v);
            unsigned lb = tf32_rna(v - __uint_as_float(hb));
            smu[OFF_BH + r * B_STRIDE + c] = hb;
            smu[OFF_BL + r * B_STRIDE + c] = lb;
        }
        __syncthreads();

        #pragma unroll
        for (int ks = 0; ks < 8; ks++) {
            int kk = ks * 8;
            const unsigned* Ah = smu + OFF_AH + (wr0 + g) * A_STRIDE + kk + t4;
            const unsigned* Al = smu + OFF_AL + (wr0 + g) * A_STRIDE + kk + t4;
            unsigned ah0 = Ah[0];
            unsigned ah1 = Ah[8 * A_STRIDE];
            unsigned ah2 = Ah[4];
            unsigned ah3 = Ah[8 * A_STRIDE + 4];
            unsigned al0 = Al[0];
            unsigned al1 = Al[8 * A_STRIDE];
            unsigned al2 = Al[4];
            unsigned al3 = Al[8 * A_STRIDE + 4];

            const unsigned* Bh = smu + OFF_BH + (kk + t4) * B_STRIDE + g;
            const unsigned* Bl = smu + OFF_BL + (kk + t4) * B_STRIDE + g;
            #pragma unroll
            for (int nt = 0; nt < 16; nt++) {
                unsigned bh0 = Bh[nt * 8];
                unsigned bh1 = Bh[4 * B_STRIDE + nt * 8];
                unsigned bl0 = Bl[nt * 8];
                unsigned bl1 = Bl[4 * B_STRIDE + nt * 8];
                mma_tf32(acc[nt], ah0, ah1, ah2, ah3, bh0, bh1);
                mma_tf32(acc[nt], ah0, ah1, ah2, ah3, bl0, bl1);
                mma_tf32(acc[nt], al0, al1, al2, al3, bh0, bh1);
            }
        }
    }

    int row0 = block_row + wr0 + g;
    int row1 = row0 + 8;
    float dinv0 = (row0 < N) ? rsqrtf((float)(g_cnt[row0] + 1)) : 0.0f;
    float dinv1 = (row1 < N) ? rsqrtf((float)(g_cnt[row1] + 1)) : 0.0f;

    #pragma unroll
    for (int nt = 0; nt < 16; nt++) {
        int col = nt * 8 + 2 * t4;
        if (row0 < N) {
            float2 o = make_float2(acc[nt][0] * dinv0, acc[nt][1] * dinv0);
            *(float2*)&g_xws[(size_t)row0 * LDIM + col] = o;
        }
        if (row1 < N) {
            float2 o = make_float2(acc[nt][2] * dinv1, acc[nt][3] * dinv1);
            *(float2*)&g_xws[(size_t)row1 * LDIM + col] = o;
        }
    }
}

// ---------------------------------------------------------------------------
// K5: one warp per node: reg-accumulate neighbors, fused finalize + softmax.
// ---------------------------------------------------------------------------
__global__ void gather_finalize_kernel(const float* __restrict__ b,
                                       float* __restrict__ out, int N)
{
    int gw = (blockIdx.x * blockDim.x + threadIdx.x) >> 5;
    int lane = threadIdx.x & 31;
    if (gw >= N) return;

    int start = g_off[gw];
    int len   = g_cnt[gw];
    const size_t lbase = (size_t)lane * 4;

    float4 acc = make_float4(0.f, 0.f, 0.f, 0.f);

    for (int base = 0; base < len; base += 32) {
        int idx = 0;
        if (base + lane < len) idx = __ldg(&g_adj[start + base + lane]);
        int m = min(32, len - base);
        int j = 0;
        for (; j + 8 <= m; j += 8) {
            int s0 = __shfl_sync(0xFFFFFFFFu, idx, j + 0);
            int s1 = __shfl_sync(0xFFFFFFFFu, idx, j + 1);
            int s2 = __shfl_sync(0xFFFFFFFFu, idx, j + 2);
            int s3 = __shfl_sync(0xFFFFFFFFu, idx, j + 3);
            int s4 = __shfl_sync(0xFFFFFFFFu, idx, j + 4);
            int s5 = __shfl_sync(0xFFFFFFFFu, idx, j + 5);
            int s6 = __shfl_sync(0xFFFFFFFFu, idx, j + 6);
            int s7 = __shfl_sync(0xFFFFFFFFu, idx, j + 7);
            float4 v0 = *(const float4*)&g_xws[(size_t)s0 * LDIM + lbase];
            float4 v1 = *(const float4*)&g_xws[(size_t)s1 * LDIM + lbase];
            float4 v2 = *(const float4*)&g_xws[(size_t)s2 * LDIM + lbase];
            float4 v3 = *(const float4*)&g_xws[(size_t)s3 * LDIM + lbase];
            float4 v4 = *(const float4*)&g_xws[(size_t)s4 * LDIM + lbase];
            float4 v5 = *(const float4*)&g_xws[(size_t)s5 * LDIM + lbase];
            float4 v6 = *(const float4*)&g_xws[(size_t)s6 * LDIM + lbase];
            float4 v7 = *(const float4*)&g_xws[(size_t)s7 * LDIM + lbase];
            acc.x += v0.x + v1.x + v2.x + v3.x + v4.x + v5.x + v6.x + v7.x;
            acc.y += v0.y + v1.y + v2.y + v3.y + v4.y + v5.y + v6.y + v7.y;
            acc.z += v0.z + v1.z + v2.z + v3.z + v4.z + v5.z + v6.z + v7.z;
            acc.w += v0.w + v1.w + v2.w + v3.w + v4.w + v5.w + v6.w + v7.w;
        }
        for (; j < m; j++) {
            int s = __shfl_sync(0xFFFFFFFFu, idx, j);
            float4 v = *(const float4*)&g_xws[(size_t)s * LDIM + lbase];
            acc.x += v.x; acc.y += v.y; acc.z += v.z; acc.w += v.w;
        }
    }

    float4 w  = *(const float4*)&g_xws[(size_t)gw * LDIM + lbase];
    float4 bb = *(const float4*)&b[lbase];
    float dinv = rsqrtf((float)(len + 1));

    float v0 = fmaxf(fmaf(dinv, acc.x + w.x, bb.x), 0.0f);
    float v1 = fmaxf(fmaf(dinv, acc.y + w.y, bb.y), 0.0f);
    float v2 = fmaxf(fmaf(dinv, acc.z + w.z, bb.z), 0.0f);
    float v3 = fmaxf(fmaf(dinv, acc.w + w.w, bb.w), 0.0f);

    float m = fmaxf(fmaxf(v0, v1), fmaxf(v2, v3));
    #pragma unroll
    for (int off = 16; off > 0; off >>= 1)
        m = fmaxf(m, __shfl_xor_sync(0xFFFFFFFFu, m, off));

    float e0 = __expf(v0 - m);
    float e1 = __expf(v1 - m);
    float e2 = __expf(v2 - m);
    float e3 = __expf(v3 - m);
    float s = e0 + e1 + e2 + e3;
    #pragma unroll
    for (int off = 16; off > 0; off >>= 1)
        s += __shfl_xor_sync(0xFFFFFFFFu, s, off);

    float inv = __frcp_rn(s);
    float4 o;
    o.x = e0 * inv; o.y = e1 * inv; o.z = e2 * inv; o.w = e3 * inv;
    *(float4*)&out[(size_t)gw * LDIM + lbase] = o;
}

// ---------------------------------------------------------------------------
extern "C" void kernel_launch(void* const* d_in, const int* in_sizes, int n_in,
                              void* d_out, int out_size)
{
    const float* x  = (const float*)d_in[0];
    const int*   ei = (const int*)d_in[1];
    const float* W  = (const float*)d_in[2];
    const float* b  = (const float*)d_in[3];
    float* out = (float*)d_out;

    int N = in_sizes[0] / LDIM;   // 50000
    int E = in_sizes[1] / 2;      // 800000
    const int* src = ei;
    const int* dst = ei + E;
    int nchunk = (N + SCAN_BLK - 1) / SCAN_BLK;

    zero_kernel<<<(N + 255) / 256, 256>>>(N);
    hist_kernel<<<(E + 255) / 256, 256>>>(dst, E);
    scan1_kernel<<<nchunk, SCAN_BLK>>>(N);
    scan2_kernel<<<1, 32>>>(nchunk);
    scan3_kernel<<<nchunk, SCAN_BLK>>>(N);
    fill_kernel<<<(E + 255) / 256, 256>>>(src, dst, E);

    cudaFuncSetAttribute(gemm_mma_kernel,
                         cudaFuncAttributeMaxDynamicSharedMemorySize, GEMM_SMEM);
    gemm_mma_kernel<<<(N + 127) / 128, 256, GEMM_SMEM>>>(x, W, N);

    long long gthreads = (long long)N * 32;
    gather_finalize_kernel<<<(int)((gthreads + 255) / 256), 256>>>(b, out, N);
}

// round 9
// speedup vs baseline: 1.8096x; 1.1800x over previous
#include <cuda_runtime.h>

#define LDIM 128
#define NMAX 50000
#define EMAX 800000
#define SCAN_BLK 1024
#define NCHUNK_MAX ((NMAX + SCAN_BLK - 1) / SCAN_BLK)

// Scratch (allocation-free rule: __device__ globals)
__device__ __align__(16) float g_xws[(size_t)NMAX * LDIM]; // (x@W)*dinv[row]
__device__ int g_cnt[NMAX];      // in-degree (excl. self loop)
__device__ int g_off[NMAX];      // CSR offsets
__device__ int g_cur[NMAX];      // fill cursors (init = g_off)
__device__ int g_adj[EMAX];      // src indices bucketed by dst
__device__ volatile int g_look[NCHUNK_MAX]; // lookback words: 0=empty, agg+1

// ---------------------------------------------------------------------------
// K0: zero counters + lookback words
// ---------------------------------------------------------------------------
__global__ void zero_kernel(int N, int nchunk) {
    int i = blockIdx.x * blockDim.x + threadIdx.x;
    if (i < N) g_cnt[i] = 0;
    if (i < nchunk) g_look[i] = 0;
}

// ---------------------------------------------------------------------------
// K1: histogram of dst
// ---------------------------------------------------------------------------
__global__ void hist_kernel(const int* __restrict__ dst, int E) {
    int e = blockIdx.x * blockDim.x + threadIdx.x;
    if (e < E) atomicAdd(&g_cnt[dst[e]], 1);
}

// ---------------------------------------------------------------------------
// K2: single-kernel exclusive scan with decoupled lookback (49 blocks).
// Publishes agg+1 in one word (single-word atomicity -> no fence needed).
// Writes g_off and seeds g_cur.
// ---------------------------------------------------------------------------
__global__ __launch_bounds__(SCAN_BLK) void scan_lookback_kernel(int N) {
    __shared__ int warpsum[32];
    __shared__ int s_prefix;
    int t = threadIdx.x, lane = t & 31, wid = t >> 5;
    int bid = blockIdx.x;
    int gid = bid * SCAN_BLK + t;
    int v = (gid < N) ? g_cnt[gid] : 0;

    // block-local inclusive scan
    int x = v;
    #pragma unroll
    for (int off = 1; off < 32; off <<= 1) {
        int y = __shfl_up_sync(0xFFFFFFFFu, x, off);
        if (lane >= off) x += y;
    }
    if (lane == 31) warpsum[wid] = x;
    __syncthreads();
    if (wid == 0) {
        int w = warpsum[lane];
        #pragma unroll
        for (int off = 1; off < 32; off <<= 1) {
            int y = __shfl_up_sync(0xFFFFFFFFu, w, off);
            if (lane >= off) w += y;
        }
        warpsum[lane] = w;
    }
    __syncthreads();
    int warp_prefix = (wid == 0) ? 0 : warpsum[wid - 1];
    int block_total = warpsum[31];

    // publish aggregate (single word, value = agg+1)
    if (t == 0) g_look[bid] = block_total + 1;

    // warp 0: gather predecessor aggregates in parallel (<=48 predecessors)
    if (wid == 0) {
        int acc = 0;
        for (int base = 0; base < bid; base += 32) {
            int j = base + lane;
            int val = 0;
            if (j < bid) {
                do { val = g_look[j]; } while (val == 0);
                val -= 1;
            }
            #pragma unroll
            for (int off = 16; off > 0; off >>= 1)
                val += __shfl_xor_sync(0xFFFFFFFFu, val, off);
            acc += val;
        }
        if (lane == 0) s_prefix = acc;
    }
    __syncthreads();

    int o = s_prefix + warp_prefix + x - v;
    if (gid < N) { g_off[gid] = o; g_cur[gid] = o; }
}

// ---------------------------------------------------------------------------
// K3: bucket fill: adj[cur[d]++] = src
// ---------------------------------------------------------------------------
__global__ void fill_kernel(const int* __restrict__ src,
                            const int* __restrict__ dst, int E) {
    int e = blockIdx.x * blockDim.x + threadIdx.x;
    if (e >= E) return;
    int d = dst[e];
    int pos = atomicAdd(&g_cur[d], 1);
    g_adj[pos] = src[e];
}

// ---------------------------------------------------------------------------
// K4: tensor-core GEMM via mma.sync m16n8k8 tf32, 3xTF32 compensation.
// A kept as raw fp32 in smem (hi/lo split in registers); B pre-split hi/lo.
// smem ~102KB -> 2 CTAs/SM.
// ---------------------------------------------------------------------------
#define A_STRIDE 68
#define B_STRIDE 136
#define OFF_A 0
#define OFF_BH (128 * A_STRIDE)
#define OFF_BL (128 * A_STRIDE + 64 * B_STRIDE)
#define GEMM_SMEM ((128 * A_STRIDE + 2 * 64 * B_STRIDE) * 4)

__device__ __forceinline__ unsigned tf32_rna(float v) {
    unsigned h;
    asm("cvt.rna.tf32.f32 %0, %1;" : "=r"(h) : "f"(v));
    return h;
}

__device__ __forceinline__ void mma_tf32(float* c,
                                         unsigned a0, unsigned a1,
                                         unsigned a2, unsigned a3,
                                         unsigned b0, unsigned b1) {
    asm volatile(
        "mma.sync.aligned.m16n8k8.row.col.f32.tf32.tf32.f32 "
        "{%0,%1,%2,%3}, {%4,%5,%6,%7}, {%8,%9}, {%0,%1,%2,%3};"
        : "+f"(c[0]), "+f"(c[1]), "+f"(c[2]), "+f"(c[3])
        : "r"(a0), "r"(a1), "r"(a2), "r"(a3), "r"(b0), "r"(b1));
}

__global__ __launch_bounds__(256) void gemm_mma_kernel(
    const float* __restrict__ x, const float* __restrict__ W, int N)
{
    extern __shared__ unsigned smu[];
    float* smf = (float*)smu;
    const int tid = threadIdx.x;
    const int wid = tid >> 5;
    const int lane = tid & 31;
    const int g = lane >> 2;
    const int t4 = lane & 3;
    const int block_row = blockIdx.x * 128;
    const int wr0 = wid * 16;

    float acc[16][4];
    #pragma unroll
    for (int nt = 0; nt < 16; nt++)
        #pragma unroll
        for (int j = 0; j < 4; j++) acc[nt][j] = 0.0f;

    #pragma unroll 1
    for (int stage = 0; stage < 2; stage++) {
        int k0 = stage * 64;
        if (stage) __syncthreads();

        // stage A raw fp32: 128 rows x 64 cols
        for (int i = tid; i < 128 * 64; i += 256) {
            int r = i >> 6, c = i & 63;
            int grow = block_row + r;
            float v = (grow < N) ? __ldg(&x[(size_t)grow * LDIM + k0 + c]) : 0.0f;
            smf[OFF_A + r * A_STRIDE + c] = v;
        }
        // stage B hi/lo: W rows k0..k0+63, 128 cols
        for (int i = tid; i < 64 * 128; i += 256) {
            int r = i >> 7, c = i & 127;
            float v = __ldg(&W[(size_t)(k0 + r) * LDIM + c]);
            unsigned hb = tf32_rna(v);
            unsigned lb = tf32_rna(v - __uint_as_float(hb));
            smu[OFF_BH + r * B_STRIDE + c] = hb;
            smu[OFF_BL + r * B_STRIDE + c] = lb;
        }
        __syncthreads();

        #pragma unroll
        for (int ks = 0; ks < 8; ks++) {
            int kk = ks * 8;
            const float* Af = smf + OFF_A + (wr0 + g) * A_STRIDE + kk + t4;
            float a0f = Af[0];
            float a1f = Af[8 * A_STRIDE];
            float a2f = Af[4];
            float a3f = Af[8 * A_STRIDE + 4];
            unsigned ah0 = tf32_rna(a0f), al0 = tf32_rna(a0f - __uint_as_float(ah0));
            unsigned ah1 = tf32_rna(a1f), al1 = tf32_rna(a1f - __uint_as_float(ah1));
            unsigned ah2 = tf32_rna(a2f), al2 = tf32_rna(a2f - __uint_as_float(ah2));
            unsigned ah3 = tf32_rna(a3f), al3 = tf32_rna(a3f - __uint_as_float(ah3));

            const unsigned* Bh = smu + OFF_BH + (kk + t4) * B_STRIDE + g;
            const unsigned* Bl = smu + OFF_BL + (kk + t4) * B_STRIDE + g;
            #pragma unroll
            for (int nt = 0; nt < 16; nt++) {
                unsigned bh0 = Bh[nt * 8];
                unsigned bh1 = Bh[4 * B_STRIDE + nt * 8];
                unsigned bl0 = Bl[nt * 8];
                unsigned bl1 = Bl[4 * B_STRIDE + nt * 8];
                mma_tf32(acc[nt], ah0, ah1, ah2, ah3, bh0, bh1);
                mma_tf32(acc[nt], ah0, ah1, ah2, ah3, bl0, bl1);
                mma_tf32(acc[nt], al0, al1, al2, al3, bh0, bh1);
            }
        }
    }

    int row0 = block_row + wr0 + g;
    int row1 = row0 + 8;
    float dinv0 = (row0 < N) ? rsqrtf((float)(g_cnt[row0] + 1)) : 0.0f;
    float dinv1 = (row1 < N) ? rsqrtf((float)(g_cnt[row1] + 1)) : 0.0f;

    #pragma unroll
    for (int nt = 0; nt < 16; nt++) {
        int col = nt * 8 + 2 * t4;
        if (row0 < N) {
            float2 o = make_float2(acc[nt][0] * dinv0, acc[nt][1] * dinv0);
            *(float2*)&g_xws[(size_t)row0 * LDIM + col] = o;
        }
        if (row1 < N) {
            float2 o = make_float2(acc[nt][2] * dinv1, acc[nt][3] * dinv1);
            *(float2*)&g_xws[(size_t)row1 * LDIM + col] = o;
        }
    }
}

// ---------------------------------------------------------------------------
// K5: one warp per node: reg-accumulate neighbors, fused finalize + softmax.
// ---------------------------------------------------------------------------
__global__ void gather_finalize_kernel(const float* __restrict__ b,
                                       float* __restrict__ out, int N)
{
    int gw = (blockIdx.x * blockDim.x + threadIdx.x) >> 5;
    int lane = threadIdx.x & 31;
    if (gw >= N) return;

    int start = g_off[gw];
    int len   = g_cnt[gw];
    const size_t lbase = (size_t)lane * 4;

    float4 acc = make_float4(0.f, 0.f, 0.f, 0.f);

    for (int base = 0; base < len; base += 32) {
        int idx = 0;
        if (base + lane < len) idx = __ldg(&g_adj[start + base + lane]);
        int m = min(32, len - base);
        int j = 0;
        for (; j + 8 <= m; j += 8) {
            int s0 = __shfl_sync(0xFFFFFFFFu, idx, j + 0);
            int s1 = __shfl_sync(0xFFFFFFFFu, idx, j + 1);
            int s2 = __shfl_sync(0xFFFFFFFFu, idx, j + 2);
            int s3 = __shfl_sync(0xFFFFFFFFu, idx, j + 3);
            int s4 = __shfl_sync(0xFFFFFFFFu, idx, j + 4);
            int s5 = __shfl_sync(0xFFFFFFFFu, idx, j + 5);
            int s6 = __shfl_sync(0xFFFFFFFFu, idx, j + 6);
            int s7 = __shfl_sync(0xFFFFFFFFu, idx, j + 7);
            float4 v0 = *(const float4*)&g_xws[(size_t)s0 * LDIM + lbase];
            float4 v1 = *(const float4*)&g_xws[(size_t)s1 * LDIM + lbase];
            float4 v2 = *(const float4*)&g_xws[(size_t)s2 * LDIM + lbase];
            float4 v3 = *(const float4*)&g_xws[(size_t)s3 * LDIM + lbase];
            float4 v4 = *(const float4*)&g_xws[(size_t)s4 * LDIM + lbase];
            float4 v5 = *(const float4*)&g_xws[(size_t)s5 * LDIM + lbase];
            float4 v6 = *(const float4*)&g_xws[(size_t)s6 * LDIM + lbase];
            float4 v7 = *(const float4*)&g_xws[(size_t)s7 * LDIM + lbase];
            acc.x += v0.x + v1.x + v2.x + v3.x + v4.x + v5.x + v6.x + v7.x;
            acc.y += v0.y + v1.y + v2.y + v3.y + v4.y + v5.y + v6.y + v7.y;
            acc.z += v0.z + v1.z + v2.z + v3.z + v4.z + v5.z + v6.z + v7.z;
            acc.w += v0.w + v1.w + v2.w + v3.w + v4.w + v5.w + v6.w + v7.w;
        }
        for (; j < m; j++) {
            int s = __shfl_sync(0xFFFFFFFFu, idx, j);
            float4 v = *(const float4*)&g_xws[(size_t)s * LDIM + lbase];
            acc.x += v.x; acc.y += v.y; acc.z += v.z; acc.w += v.w;
        }
    }

    float4 w  = *(const float4*)&g_xws[(size_t)gw * LDIM + lbase];
    float4 bb = *(const float4*)&b[lbase];
    float dinv = rsqrtf((float)(len + 1));

    float v0 = fmaxf(fmaf(dinv, acc.x + w.x, bb.x), 0.0f);
    float v1 = fmaxf(fmaf(dinv, acc.y + w.y, bb.y), 0.0f);
    float v2 = fmaxf(fmaf(dinv, acc.z + w.z, bb.z), 0.0f);
    float v3 = fmaxf(fmaf(dinv, acc.w + w.w, bb.w), 0.0f);

    float m = fmaxf(fmaxf(v0, v1), fmaxf(v2, v3));
    #pragma unroll
    for (int off = 16; off > 0; off >>= 1)
        m = fmaxf(m, __shfl_xor_sync(0xFFFFFFFFu, m, off));

    float e0 = __expf(v0 - m);
    float e1 = __expf(v1 - m);
    float e2 = __expf(v2 - m);
    float e3 = __expf(v3 - m);
    float s = e0 + e1 + e2 + e3;
    #pragma unroll
    for (int off = 16; off > 0; off >>= 1)
        s += __shfl_xor_sync(0xFFFFFFFFu, s, off);

    float inv = __frcp_rn(s);
    float4 o;
    o.x = e0 * inv; o.y = e1 * inv; o.z = e2 * inv; o.w = e3 * inv;
    *(float4*)&out[(size_t)gw * LDIM + lbase] = o;
}

// ---------------------------------------------------------------------------
extern "C" void kernel_launch(void* const* d_in, const int* in_sizes, int n_in,
                              void* d_out, int out_size)
{
    const float* x  = (const float*)d_in[0];
    const int*   ei = (const int*)d_in[1];
    const float* W  = (const float*)d_in[2];
    const float* b  = (const float*)d_in[3];
    float* out = (float*)d_out;

    int N = in_sizes[0] / LDIM;   // 50000
    int E = in_sizes[1] / 2;      // 800000
    const int* src = ei;
    const int* dst = ei + E;
    int nchunk = (N + SCAN_BLK - 1) / SCAN_BLK;

    zero_kernel<<<(N + 255) / 256, 256>>>(N, nchunk);
    hist_kernel<<<(E + 255) / 256, 256>>>(dst, E);
    scan_lookback_kernel<<<nchunk, SCAN_BLK>>>(N);

    // 4th launch -> lands in the ncu profiling window
    cudaFuncSetAttribute(gemm_mma_kernel,
                         cudaFuncAttributeMaxDynamicSharedMemorySize, GEMM_SMEM);
    gemm_mma_kernel<<<(N + 127) / 128, 256, GEMM_SMEM>>>(x, W, N);

    fill_kernel<<<(E + 255) / 256, 256>>>(src, dst, E);

    long long gthreads = (long long)N * 32;
    gather_finalize_kernel<<<(int)((gthreads + 255) / 256), 256>>>(b, out, N);
}

// round 10
// speedup vs baseline: 1.9184x; 1.0601x over previous
#include <cuda_runtime.h>

#define LDIM 128
#define NMAX 50000
#define EMAX 800000
#define SCAN_BLK 1024
#define NCHUNK_MAX ((NMAX + SCAN_BLK - 1) / SCAN_BLK)

// Scratch (allocation-free rule: __device__ globals)
__device__ __align__(16) float g_xws[(size_t)NMAX * LDIM]; // (x@W)*dinv[row]
__device__ int g_cnt[NMAX];      // in-degree (excl. self loop)
__device__ int g_off[NMAX];      // CSR offsets
__device__ int g_cur[NMAX];      // fill cursors (init = g_off)
__device__ int g_adj[EMAX];      // src indices bucketed by dst
__device__ volatile int g_look[NCHUNK_MAX]; // lookback words: 0=empty, agg+1
__device__ unsigned g_whi[LDIM * LDIM];     // W tf32 high parts
__device__ unsigned g_wlo[LDIM * LDIM];     // W tf32 low parts

__device__ __forceinline__ unsigned tf32_rna(float v) {
    unsigned h;
    asm("cvt.rna.tf32.f32 %0, %1;" : "=r"(h) : "f"(v));
    return h;
}

// ---------------------------------------------------------------------------
// K0: zero counters + lookback words
// ---------------------------------------------------------------------------
__global__ void zero_kernel(int N, int nchunk) {
    int i = blockIdx.x * blockDim.x + threadIdx.x;
    if (i < N) g_cnt[i] = 0;
    if (i < nchunk) g_look[i] = 0;
}

// ---------------------------------------------------------------------------
// K1: histogram of dst
// ---------------------------------------------------------------------------
__global__ void hist_kernel(const int* __restrict__ dst, int E) {
    int e = blockIdx.x * blockDim.x + threadIdx.x;
    if (e < E) atomicAdd(&g_cnt[dst[e]], 1);
}

// ---------------------------------------------------------------------------
// K1b: one-shot W -> tf32 hi/lo split (amortized over all GEMM CTAs)
// ---------------------------------------------------------------------------
__global__ void wsplit_kernel(const float* __restrict__ W) {
    int i = blockIdx.x * blockDim.x + threadIdx.x;
    if (i < LDIM * LDIM) {
        float v = W[i];
        unsigned hb = tf32_rna(v);
        g_whi[i] = hb;
        g_wlo[i] = tf32_rna(v - __uint_as_float(hb));
    }
}

// ---------------------------------------------------------------------------
// K2: single-kernel exclusive scan with decoupled lookback (49 blocks).
// ---------------------------------------------------------------------------
__global__ __launch_bounds__(SCAN_BLK) void scan_lookback_kernel(int N) {
    __shared__ int warpsum[32];
    __shared__ int s_prefix;
    int t = threadIdx.x, lane = t & 31, wid = t >> 5;
    int bid = blockIdx.x;
    int gid = bid * SCAN_BLK + t;
    int v = (gid < N) ? g_cnt[gid] : 0;

    int x = v;
    #pragma unroll
    for (int off = 1; off < 32; off <<= 1) {
        int y = __shfl_up_sync(0xFFFFFFFFu, x, off);
        if (lane >= off) x += y;
    }
    if (lane == 31) warpsum[wid] = x;
    __syncthreads();
    if (wid == 0) {
        int w = warpsum[lane];
        #pragma unroll
        for (int off = 1; off < 32; off <<= 1) {
            int y = __shfl_up_sync(0xFFFFFFFFu, w, off);
            if (lane >= off) w += y;
        }
        warpsum[lane] = w;
    }
    __syncthreads();
    int warp_prefix = (wid == 0) ? 0 : warpsum[wid - 1];
    int block_total = warpsum[31];

    if (t == 0) g_look[bid] = block_total + 1;

    if (wid == 0) {
        int acc = 0;
        for (int base = 0; base < bid; base += 32) {
            int j = base + lane;
            int val = 0;
            if (j < bid) {
                do { val = g_look[j]; } while (val == 0);
                val -= 1;
            }
            #pragma unroll
            for (int off = 16; off > 0; off >>= 1)
                val += __shfl_xor_sync(0xFFFFFFFFu, val, off);
            acc += val;
        }
        if (lane == 0) s_prefix = acc;
    }
    __syncthreads();

    int o = s_prefix + warp_prefix + x - v;
    if (gid < N) { g_off[gid] = o; g_cur[gid] = o; }
}

// ---------------------------------------------------------------------------
// K3: bucket fill
// ---------------------------------------------------------------------------
__global__ void fill_kernel(const int* __restrict__ src,
                            const int* __restrict__ dst, int E) {
    int e = blockIdx.x * blockDim.x + threadIdx.x;
    if (e >= E) return;
    int d = dst[e];
    int pos = atomicAdd(&g_cur[d], 1);
    g_adj[pos] = src[e];
}

// ---------------------------------------------------------------------------
// K4: mma.sync tf32 GEMM, 3xTF32. 512 threads/CTA, 128x128 tile.
// 16 warps = 8 row-groups x 2 col-groups; acc 8x4 per thread.
// A raw fp32 in smem (reg-split); B hi/lo copied from precomputed g_whi/g_wlo.
// ---------------------------------------------------------------------------
#define A_STRIDE 68
#define B_STRIDE 136
#define OFF_A 0
#define OFF_BH (128 * A_STRIDE)
#define OFF_BL (128 * A_STRIDE + 64 * B_STRIDE)
#define GEMM_SMEM ((128 * A_STRIDE + 2 * 64 * B_STRIDE) * 4)

__device__ __forceinline__ void mma_tf32(float* c,
                                         unsigned a0, unsigned a1,
                                         unsigned a2, unsigned a3,
                                         unsigned b0, unsigned b1) {
    asm volatile(
        "mma.sync.aligned.m16n8k8.row.col.f32.tf32.tf32.f32 "
        "{%0,%1,%2,%3}, {%4,%5,%6,%7}, {%8,%9}, {%0,%1,%2,%3};"
        : "+f"(c[0]), "+f"(c[1]), "+f"(c[2]), "+f"(c[3])
        : "r"(a0), "r"(a1), "r"(a2), "r"(a3), "r"(b0), "r"(b1));
}

__global__ __launch_bounds__(512, 2) void gemm_mma_kernel(
    const float* __restrict__ x, int N)
{
    extern __shared__ unsigned smu[];
    float* smf = (float*)smu;
    const int tid = threadIdx.x;
    const int wid = tid >> 5;
    const int lane = tid & 31;
    const int g = lane >> 2;
    const int t4 = lane & 3;
    const int block_row = blockIdx.x * 128;
    const int wr0 = (wid >> 1) * 16;   // 8 row-groups of 16
    const int wc0 = (wid & 1) * 64;    // 2 col-groups of 64

    float acc[8][4];
    #pragma unroll
    for (int nt = 0; nt < 8; nt++)
        #pragma unroll
        for (int j = 0; j < 4; j++) acc[nt][j] = 0.0f;

    #pragma unroll 1
    for (int stage = 0; stage < 2; stage++) {
        int k0 = stage * 64;
        if (stage) __syncthreads();

        // stage A raw fp32: 128 rows x 64 cols
        for (int i = tid; i < 128 * 64; i += 512) {
            int r = i >> 6, c = i & 63;
            int grow = block_row + r;
            float v = (grow < N) ? __ldg(&x[(size_t)grow * LDIM + k0 + c]) : 0.0f;
            smf[OFF_A + r * A_STRIDE + c] = v;
        }
        // stage B hi/lo: straight copies of precomputed splits
        for (int i = tid; i < 64 * 128; i += 512) {
            int r = i >> 7, c = i & 127;
            smu[OFF_BH + r * B_STRIDE + c] = g_whi[(k0 + r) * LDIM + c];
            smu[OFF_BL + r * B_STRIDE + c] = g_wlo[(k0 + r) * LDIM + c];
        }
        __syncthreads();

        #pragma unroll
        for (int ks = 0; ks < 8; ks++) {
            int kk = ks * 8;
            const float* Af = smf + OFF_A + (wr0 + g) * A_STRIDE + kk + t4;
            float a0f = Af[0];
            float a1f = Af[8 * A_STRIDE];
            float a2f = Af[4];
            float a3f = Af[8 * A_STRIDE + 4];
            unsigned ah0 = tf32_rna(a0f), al0 = tf32_rna(a0f - __uint_as_float(ah0));
            unsigned ah1 = tf32_rna(a1f), al1 = tf32_rna(a1f - __uint_as_float(ah1));
            unsigned ah2 = tf32_rna(a2f), al2 = tf32_rna(a2f - __uint_as_float(ah2));
            unsigned ah3 = tf32_rna(a3f), al3 = tf32_rna(a3f - __uint_as_float(ah3));

            const unsigned* Bh = smu + OFF_BH + (kk + t4) * B_STRIDE + wc0 + g;
            const unsigned* Bl = smu + OFF_BL + (kk + t4) * B_STRIDE + wc0 + g;
            #pragma unroll
            for (int nt = 0; nt < 8; nt++) {
                unsigned bh0 = Bh[nt * 8];
                unsigned bh1 = Bh[4 * B_STRIDE + nt * 8];
                unsigned bl0 = Bl[nt * 8];
                unsigned bl1 = Bl[4 * B_STRIDE + nt * 8];
                mma_tf32(acc[nt], ah0, ah1, ah2, ah3, bh0, bh1);
                mma_tf32(acc[nt], ah0, ah1, ah2, ah3, bl0, bl1);
                mma_tf32(acc[nt], al0, al1, al2, al3, bh0, bh1);
            }
        }
    }

    int row0 = block_row + wr0 + g;
    int row1 = row0 + 8;
    float dinv0 = (row0 < N) ? rsqrtf((float)(g_cnt[row0] + 1)) : 0.0f;
    float dinv1 = (row1 < N) ? rsqrtf((float)(g_cnt[row1] + 1)) : 0.0f;

    #pragma unroll
    for (int nt = 0; nt < 8; nt++) {
        int col = wc0 + nt * 8 + 2 * t4;
        if (row0 < N) {
            float2 o = make_float2(acc[nt][0] * dinv0, acc[nt][1] * dinv0);
            *(float2*)&g_xws[(size_t)row0 * LDIM + col] = o;
        }
        if (row1 < N) {
            float2 o = make_float2(acc[nt][2] * dinv1, acc[nt][3] * dinv1);
            *(float2*)&g_xws[(size_t)row1 * LDIM + col] = o;
        }
    }
}

// ---------------------------------------------------------------------------
// K5: one warp per node: reg-accumulate neighbors, fused finalize + softmax.
// ---------------------------------------------------------------------------
__global__ void gather_finalize_kernel(const float* __restrict__ b,
                                       float* __restrict__ out, int N)
{
    int gw = (blockIdx.x * blockDim.x + threadIdx.x) >> 5;
    int lane = threadIdx.x & 31;
    if (gw >= N) return;

    int start = g_off[gw];
    int len   = g_cnt[gw];
    const size_t lbase = (size_t)lane * 4;

    float4 acc = make_float4(0.f, 0.f, 0.f, 0.f);

    for (int base = 0; base < len; base += 32) {
        int idx = 0;
        if (base + lane < len) idx = __ldg(&g_adj[start + base + lane]);
        int m = min(32, len - base);
        int j = 0;
        for (; j + 8 <= m; j += 8) {
            int s0 = __shfl_sync(0xFFFFFFFFu, idx, j + 0);
            int s1 = __shfl_sync(0xFFFFFFFFu, idx, j + 1);
            int s2 = __shfl_sync(0xFFFFFFFFu, idx, j + 2);
            int s3 = __shfl_sync(0xFFFFFFFFu, idx, j + 3);
            int s4 = __shfl_sync(0xFFFFFFFFu, idx, j + 4);
            int s5 = __shfl_sync(0xFFFFFFFFu, idx, j + 5);
            int s6 = __shfl_sync(0xFFFFFFFFu, idx, j + 6);
            int s7 = __shfl_sync(0xFFFFFFFFu, idx, j + 7);
            float4 v0 = *(const float4*)&g_xws[(size_t)s0 * LDIM + lbase];
            float4 v1 = *(const float4*)&g_xws[(size_t)s1 * LDIM + lbase];
            float4 v2 = *(const float4*)&g_xws[(size_t)s2 * LDIM + lbase];
            float4 v3 = *(const float4*)&g_xws[(size_t)s3 * LDIM + lbase];
            float4 v4 = *(const float4*)&g_xws[(size_t)s4 * LDIM + lbase];
            float4 v5 = *(const float4*)&g_xws[(size_t)s5 * LDIM + lbase];
            float4 v6 = *(const float4*)&g_xws[(size_t)s6 * LDIM + lbase];
            float4 v7 = *(const float4*)&g_xws[(size_t)s7 * LDIM + lbase];
            acc.x += v0.x + v1.x + v2.x + v3.x + v4.x + v5.x + v6.x + v7.x;
            acc.y += v0.y + v1.y + v2.y + v3.y + v4.y + v5.y + v6.y + v7.y;
            acc.z += v0.z + v1.z + v2.z + v3.z + v4.z + v5.z + v6.z + v7.z;
            acc.w += v0.w + v1.w + v2.w + v3.w + v4.w + v5.w + v6.w + v7.w;
        }
        for (; j < m; j++) {
            int s = __shfl_sync(0xFFFFFFFFu, idx, j);
            float4 v = *(const float4*)&g_xws[(size_t)s * LDIM + lbase];
            acc.x += v.x; acc.y += v.y; acc.z += v.z; acc.w += v.w;
        }
    }

    float4 w  = *(const float4*)&g_xws[(size_t)gw * LDIM + lbase];
    float4 bb = *(const float4*)&b[lbase];
    float dinv = rsqrtf((float)(len + 1));

    float v0 = fmaxf(fmaf(dinv, acc.x + w.x, bb.x), 0.0f);
    float v1 = fmaxf(fmaf(dinv, acc.y + w.y, bb.y), 0.0f);
    float v2 = fmaxf(fmaf(dinv, acc.z + w.z, bb.z), 0.0f);
    float v3 = fmaxf(fmaf(dinv, acc.w + w.w, bb.w), 0.0f);

    float m = fmaxf(fmaxf(v0, v1), fmaxf(v2, v3));
    #pragma unroll
    for (int off = 16; off > 0; off >>= 1)
        m = fmaxf(m, __shfl_xor_sync(0xFFFFFFFFu, m, off));

    float e0 = __expf(v0 - m);
    float e1 = __expf(v1 - m);
    float e2 = __expf(v2 - m);
    float e3 = __expf(v3 - m);
    float s = e0 + e1 + e2 + e3;
    #pragma unroll
    for (int off = 16; off > 0; off >>= 1)
        s += __shfl_xor_sync(0xFFFFFFFFu, s, off);

    float inv = __frcp_rn(s);
    float4 o;
    o.x = e0 * inv; o.y = e1 * inv; o.z = e2 * inv; o.w = e3 * inv;
    *(float4*)&out[(size_t)gw * LDIM + lbase] = o;
}

// ---------------------------------------------------------------------------
extern "C" void kernel_launch(void* const* d_in, const int* in_sizes, int n_in,
                              void* d_out, int out_size)
{
    const float* x  = (const float*)d_in[0];
    const int*   ei = (const int*)d_in[1];
    const float* W  = (const float*)d_in[2];
    const float* b  = (const float*)d_in[3];
    float* out = (float*)d_out;

    int N = in_sizes[0] / LDIM;   // 50000
    int E = in_sizes[1] / 2;      // 800000
    const int* src = ei;
    const int* dst = ei + E;
    int nchunk = (N + SCAN_BLK - 1) / SCAN_BLK;

    zero_kernel<<<(N + 255) / 256, 256>>>(N, nchunk);
    hist_kernel<<<(E + 255) / 256, 256>>>(dst, E);
    wsplit_kernel<<<(LDIM * LDIM + 255) / 256, 256>>>(W);

    // 4th launch -> ncu profiling window: verify GEMM occupancy fix
    cudaFuncSetAttribute(gemm_mma_kernel,
                         cudaFuncAttributeMaxDynamicSharedMemorySize, GEMM_SMEM);
    gemm_mma_kernel<<<(N + 127) / 128, 512, GEMM_SMEM>>>(x, N);

    scan_lookback_kernel<<<nchunk, SCAN_BLK>>>(N);
    fill_kernel<<<(E + 255) / 256, 256>>>(src, dst, E);

    long long gthreads = (long long)N * 32;
    gather_finalize_kernel<<<(int)((gthreads + 255) / 256), 256>>>(b, out, N);
}

// round 11
// speedup vs baseline: 2.1738x; 1.1332x over previous
#include <cuda_runtime.h>

#define LDIM 128
#define NMAX 50000
#define EMAX 800000
#define SCAN_BLK 1024
#define NCHUNK_MAX ((NMAX + SCAN_BLK - 1) / SCAN_BLK)

// Scratch (allocation-free rule: __device__ globals)
__device__ __align__(16) float g_xws[(size_t)NMAX * LDIM]; // (x@W)*dinv[row]
__device__ int g_cnt[NMAX];      // in-degree (excl. self loop)
__device__ int g_off[NMAX];      // CSR offsets
__device__ int g_cur[NMAX];      // fill cursors (init = g_off)
__device__ int g_adj[EMAX];      // src indices bucketed by dst
__device__ volatile int g_look[NCHUNK_MAX]; // lookback words: 0=empty, agg+1
__device__ unsigned g_wbhi[64 * LDIM];  // W bf16 hi, packed k-pairs: [kpair][n]
__device__ unsigned g_wblo[64 * LDIM];  // W bf16 lo residuals

// ---- bf16 pack/split helpers ------------------------------------------------
__device__ __forceinline__ unsigned packbf(float x, float y) {
    // reg: lo half = bf16(x), hi half = bf16(y)
    unsigned r;
    asm("cvt.rn.bf16x2.f32 %0, %1, %2;" : "=r"(r) : "f"(y), "f"(x));
    return r;
}
__device__ __forceinline__ float bf_lo(unsigned r) { return __uint_as_float(r << 16); }
__device__ __forceinline__ float bf_hi(unsigned r) { return __uint_as_float(r & 0xFFFF0000u); }

__device__ __forceinline__ void split_bf(float x, float y, unsigned& hi, unsigned& lo) {
    hi = packbf(x, y);
    lo = packbf(x - bf_lo(hi), y - bf_hi(hi));
}

// ---------------------------------------------------------------------------
// K0: zero counters + lookback words
// ---------------------------------------------------------------------------
__global__ void zero_kernel(int N, int nchunk) {
    int i = blockIdx.x * blockDim.x + threadIdx.x;
    if (i < N) g_cnt[i] = 0;
    if (i < nchunk) g_look[i] = 0;
}

// ---------------------------------------------------------------------------
// K1: histogram of dst
// ---------------------------------------------------------------------------
__global__ void hist_kernel(const int* __restrict__ dst, int E) {
    int e = blockIdx.x * blockDim.x + threadIdx.x;
    if (e < E) atomicAdd(&g_cnt[dst[e]], 1);
}

// ---------------------------------------------------------------------------
// K1b: one-shot W -> packed bf16 hi/lo split, k-pair layout [kpair][n]
// ---------------------------------------------------------------------------
__global__ void wsplit_kernel(const float* __restrict__ W) {
    int i = blockIdx.x * blockDim.x + threadIdx.x;
    if (i < 64 * LDIM) {
        int kp = i >> 7, n = i & 127;
        float v0 = W[(2 * kp) * LDIM + n];
        float v1 = W[(2 * kp + 1) * LDIM + n];
        unsigned hi, lo;
        split_bf(v0, v1, hi, lo);
        g_wbhi[i] = hi;
        g_wblo[i] = lo;
    }
}

// ---------------------------------------------------------------------------
// K2: single-kernel exclusive scan with decoupled lookback (49 blocks)
// ---------------------------------------------------------------------------
__global__ __launch_bounds__(SCAN_BLK) void scan_lookback_kernel(int N) {
    __shared__ int warpsum[32];
    __shared__ int s_prefix;
    int t = threadIdx.x, lane = t & 31, wid = t >> 5;
    int bid = blockIdx.x;
    int gid = bid * SCAN_BLK + t;
    int v = (gid < N) ? g_cnt[gid] : 0;

    int x = v;
    #pragma unroll
    for (int off = 1; off < 32; off <<= 1) {
        int y = __shfl_up_sync(0xFFFFFFFFu, x, off);
        if (lane >= off) x += y;
    }
    if (lane == 31) warpsum[wid] = x;
    __syncthreads();
    if (wid == 0) {
        int w = warpsum[lane];
        #pragma unroll
        for (int off = 1; off < 32; off <<= 1) {
            int y = __shfl_up_sync(0xFFFFFFFFu, w, off);
            if (lane >= off) w += y;
        }
        warpsum[lane] = w;
    }
    __syncthreads();
    int warp_prefix = (wid == 0) ? 0 : warpsum[wid - 1];
    int block_total = warpsum[31];

    if (t == 0) g_look[bid] = block_total + 1;

    if (wid == 0) {
        int acc = 0;
        for (int base = 0; base < bid; base += 32) {
            int j = base + lane;
            int val = 0;
            if (j < bid) {
                do { val = g_look[j]; } while (val == 0);
                val -= 1;
            }
            #pragma unroll
            for (int off = 16; off > 0; off >>= 1)
                val += __shfl_xor_sync(0xFFFFFFFFu, val, off);
            acc += val;
        }
        if (lane == 0) s_prefix = acc;
    }
    __syncthreads();

    int o = s_prefix + warp_prefix + x - v;
    if (gid < N) { g_off[gid] = o; g_cur[gid] = o; }
}

// ---------------------------------------------------------------------------
// K3: bucket fill
// ---------------------------------------------------------------------------
__global__ void fill_kernel(const int* __restrict__ src,
                            const int* __restrict__ dst, int E) {
    int e = blockIdx.x * blockDim.x + threadIdx.x;
    if (e >= E) return;
    int d = dst[e];
    int pos = atomicAdd(&g_cur[d], 1);
    g_adj[pos] = src[e];
}

// ---------------------------------------------------------------------------
// K4: bf16 m16n8k16 GEMM with 2xBF16 split (AhBh + AhBl + AlBh).
// 512 threads, 128x128 tile, 16 warps = 8 row-groups x 2 col-groups.
// A raw fp32 in smem (reg-split to bf16x2); B packed bf16x2 hi/lo from wsplit.
// ---------------------------------------------------------------------------
#define A_STRIDE 68               // floats per A row (34 float2)
#define BP_STRIDE 136             // words per B kpair row (136 mod 32 == 8)
#define OFF_A 0
#define OFF_BH (128 * A_STRIDE)
#define OFF_BL (128 * A_STRIDE + 32 * BP_STRIDE)
#define GEMM_SMEM ((128 * A_STRIDE + 2 * 32 * BP_STRIDE) * 4)

__device__ __forceinline__ void mma_bf16(float* c,
                                         unsigned a0, unsigned a1,
                                         unsigned a2, unsigned a3,
                                         unsigned b0, unsigned b1) {
    asm volatile(
        "mma.sync.aligned.m16n8k16.row.col.f32.bf16.bf16.f32 "
        "{%0,%1,%2,%3}, {%4,%5,%6,%7}, {%8,%9}, {%0,%1,%2,%3};"
        : "+f"(c[0]), "+f"(c[1]), "+f"(c[2]), "+f"(c[3])
        : "r"(a0), "r"(a1), "r"(a2), "r"(a3), "r"(b0), "r"(b1));
}

__global__ __launch_bounds__(512, 2) void gemm_mma_kernel(
    const float* __restrict__ x, int N)
{
    extern __shared__ unsigned smu[];
    float* smf = (float*)smu;
    const int tid = threadIdx.x;
    const int wid = tid >> 5;
    const int lane = tid & 31;
    const int g = lane >> 2;
    const int t4 = lane & 3;
    const int block_row = blockIdx.x * 128;
    const int wr0 = (wid >> 1) * 16;   // 8 row-groups of 16
    const int wc0 = (wid & 1) * 64;    // 2 col-groups of 64

    float acc[8][4];
    #pragma unroll
    for (int nt = 0; nt < 8; nt++)
        #pragma unroll
        for (int j = 0; j < 4; j++) acc[nt][j] = 0.0f;

    #pragma unroll 1
    for (int stage = 0; stage < 2; stage++) {
        int k0 = stage * 64;        // element base
        int kp0 = stage * 32;       // kpair base
        if (stage) __syncthreads();

        // stage A raw fp32: 128 rows x 64 cols
        for (int i = tid; i < 128 * 64; i += 512) {
            int r = i >> 6, c = i & 63;
            int grow = block_row + r;
            float v = (grow < N) ? __ldg(&x[(size_t)grow * LDIM + k0 + c]) : 0.0f;
            smf[OFF_A + r * A_STRIDE + c] = v;
        }
        // stage B packed hi/lo: 32 kpairs x 128 n
        for (int i = tid; i < 32 * 128; i += 512) {
            int kp = i >> 7, n = i & 127;
            smu[OFF_BH + kp * BP_STRIDE + n] = g_wbhi[(kp0 + kp) * LDIM + n];
            smu[OFF_BL + kp * BP_STRIDE + n] = g_wblo[(kp0 + kp) * LDIM + n];
        }
        __syncthreads();

        #pragma unroll
        for (int ks = 0; ks < 4; ks++) {     // 4 x k16 per stage
            // A fragments: rows {wr0+g, wr0+g+8}, col pairs {t4, t4+4} within k16
            const float2* A2r0 = (const float2*)(smf + OFF_A) + (wr0 + g) * (A_STRIDE / 2) + ks * 8;
            const float2* A2r1 = A2r0 + 8 * (A_STRIDE / 2);
            float2 f0 = A2r0[t4];
            float2 f1 = A2r1[t4];
            float2 f2 = A2r0[t4 + 4];
            float2 f3 = A2r1[t4 + 4];
            unsigned ah0, al0, ah1, al1, ah2, al2, ah3, al3;
            split_bf(f0.x, f0.y, ah0, al0);
            split_bf(f1.x, f1.y, ah1, al1);
            split_bf(f2.x, f2.y, ah2, al2);
            split_bf(f3.x, f3.y, ah3, al3);

            // B fragments: kpair rows {ks*8+t4, ks*8+t4+4}, col wc0+g+nt*8
            const unsigned* Bh = smu + OFF_BH + (ks * 8 + t4) * BP_STRIDE + wc0 + g;
            const unsigned* Bl = smu + OFF_BL + (ks * 8 + t4) * BP_STRIDE + wc0 + g;
            #pragma unroll
            for (int nt = 0; nt < 8; nt++) {
                unsigned bh0 = Bh[nt * 8];
                unsigned bh1 = Bh[4 * BP_STRIDE + nt * 8];
                unsigned bl0 = Bl[nt * 8];
                unsigned bl1 = Bl[4 * BP_STRIDE + nt * 8];
                mma_bf16(acc[nt], ah0, ah1, ah2, ah3, bh0, bh1);
                mma_bf16(acc[nt], ah0, ah1, ah2, ah3, bl0, bl1);
                mma_bf16(acc[nt], al0, al1, al2, al3, bh0, bh1);
            }
        }
    }

    int row0 = block_row + wr0 + g;
    int row1 = row0 + 8;
    float dinv0 = (row0 < N) ? rsqrtf((float)(g_cnt[row0] + 1)) : 0.0f;
    float dinv1 = (row1 < N) ? rsqrtf((float)(g_cnt[row1] + 1)) : 0.0f;

    #pragma unroll
    for (int nt = 0; nt < 8; nt++) {
        int col = wc0 + nt * 8 + 2 * t4;
        if (row0 < N) {
            float2 o = make_float2(acc[nt][0] * dinv0, acc[nt][1] * dinv0);
            *(float2*)&g_xws[(size_t)row0 * LDIM + col] = o;
        }
        if (row1 < N) {
            float2 o = make_float2(acc[nt][2] * dinv1, acc[nt][3] * dinv1);
            *(float2*)&g_xws[(size_t)row1 * LDIM + col] = o;
        }
    }
}

// ---------------------------------------------------------------------------
// K5: one warp per node: reg-accumulate neighbors, fused finalize + softmax.
// ---------------------------------------------------------------------------
__global__ void gather_finalize_kernel(const float* __restrict__ b,
                                       float* __restrict__ out, int N)
{
    int gw = (blockIdx.x * blockDim.x + threadIdx.x) >> 5;
    int lane = threadIdx.x & 31;
    if (gw >= N) return;

    int start = g_off[gw];
    int len   = g_cnt[gw];
    const size_t lbase = (size_t)lane * 4;

    float4 acc = make_float4(0.f, 0.f, 0.f, 0.f);

    for (int base = 0; base < len; base += 32) {
        int idx = 0;
        if (base + lane < len) idx = __ldg(&g_adj[start + base + lane]);
        int m = min(32, len - base);
        int j = 0;
        for (; j + 8 <= m; j += 8) {
            int s0 = __shfl_sync(0xFFFFFFFFu, idx, j + 0);
            int s1 = __shfl_sync(0xFFFFFFFFu, idx, j + 1);
            int s2 = __shfl_sync(0xFFFFFFFFu, idx, j + 2);
            int s3 = __shfl_sync(0xFFFFFFFFu, idx, j + 3);
            int s4 = __shfl_sync(0xFFFFFFFFu, idx, j + 4);
            int s5 = __shfl_sync(0xFFFFFFFFu, idx, j + 5);
            int s6 = __shfl_sync(0xFFFFFFFFu, idx, j + 6);
            int s7 = __shfl_sync(0xFFFFFFFFu, idx, j + 7);
            float4 v0 = *(const float4*)&g_xws[(size_t)s0 * LDIM + lbase];
            float4 v1 = *(const float4*)&g_xws[(size_t)s1 * LDIM + lbase];
            float4 v2 = *(const float4*)&g_xws[(size_t)s2 * LDIM + lbase];
            float4 v3 = *(const float4*)&g_xws[(size_t)s3 * LDIM + lbase];
            float4 v4 = *(const float4*)&g_xws[(size_t)s4 * LDIM + lbase];
            float4 v5 = *(const float4*)&g_xws[(size_t)s5 * LDIM + lbase];
            float4 v6 = *(const float4*)&g_xws[(size_t)s6 * LDIM + lbase];
            float4 v7 = *(const float4*)&g_xws[(size_t)s7 * LDIM + lbase];
            acc.x += v0.x + v1.x + v2.x + v3.x + v4.x + v5.x + v6.x + v7.x;
            acc.y += v0.y + v1.y + v2.y + v3.y + v4.y + v5.y + v6.y + v7.y;
            acc.z += v0.z + v1.z + v2.z + v3.z + v4.z + v5.z + v6.z + v7.z;
            acc.w += v0.w + v1.w + v2.w + v3.w + v4.w + v5.w + v6.w + v7.w;
        }
        for (; j < m; j++) {
            int s = __shfl_sync(0xFFFFFFFFu, idx, j);
            float4 v = *(const float4*)&g_xws[(size_t)s * LDIM + lbase];
            acc.x += v.x; acc.y += v.y; acc.z += v.z; acc.w += v.w;
        }
    }

    float4 w  = *(const float4*)&g_xws[(size_t)gw * LDIM + lbase];
    float4 bb = *(const float4*)&b[lbase];
    float dinv = rsqrtf((float)(len + 1));

    float v0 = fmaxf(fmaf(dinv, acc.x + w.x, bb.x), 0.0f);
    float v1 = fmaxf(fmaf(dinv, acc.y + w.y, bb.y), 0.0f);
    float v2 = fmaxf(fmaf(dinv, acc.z + w.z, bb.z), 0.0f);
    float v3 = fmaxf(fmaf(dinv, acc.w + w.w, bb.w), 0.0f);

    float m = fmaxf(fmaxf(v0, v1), fmaxf(v2, v3));
    #pragma unroll
    for (int off = 16; off > 0; off >>= 1)
        m = fmaxf(m, __shfl_xor_sync(0xFFFFFFFFu, m, off));

    float e0 = __expf(v0 - m);
    float e1 = __expf(v1 - m);
    float e2 = __expf(v2 - m);
    float e3 = __expf(v3 - m);
    float s = e0 + e1 + e2 + e3;
    #pragma unroll
    for (int off = 16; off > 0; off >>= 1)
        s += __shfl_xor_sync(0xFFFFFFFFu, s, off);

    float inv = __frcp_rn(s);
    float4 o;
    o.x = e0 * inv; o.y = e1 * inv; o.z = e2 * inv; o.w = e3 * inv;
    *(float4*)&out[(size_t)gw * LDIM + lbase] = o;
}

// ---------------------------------------------------------------------------
extern "C" void kernel_launch(void* const* d_in, const int* in_sizes, int n_in,
                              void* d_out, int out_size)
{
    const float* x  = (const float*)d_in[0];
    const int*   ei = (const int*)d_in[1];
    const float* W  = (const float*)d_in[2];
    const float* b  = (const float*)d_in[3];
    float* out = (float*)d_out;

    int N = in_sizes[0] / LDIM;   // 50000
    int E = in_sizes[1] / 2;      // 800000
    const int* src = ei;
    const int* dst = ei + E;
    int nchunk = (N + SCAN_BLK - 1) / SCAN_BLK;

    zero_kernel<<<(N + 255) / 256, 256>>>(N, nchunk);
    hist_kernel<<<(E + 255) / 256, 256>>>(dst, E);
    wsplit_kernel<<<(64 * LDIM + 255) / 256, 256>>>(W);

    // 4th launch -> ncu profiling window: verify bf16 GEMM
    cudaFuncSetAttribute(gemm_mma_kernel,
                         cudaFuncAttributeMaxDynamicSharedMemorySize, GEMM_SMEM);
    gemm_mma_kernel<<<(N + 127) / 128, 512, GEMM_SMEM>>>(x, N);

    scan_lookback_kernel<<<nchunk, SCAN_BLK>>>(N);
    fill_kernel<<<(E + 255) / 256, 256>>>(src, dst, E);

    long long gthreads = (long long)N * 32;
    gather_finalize_kernel<<<(int)((gthreads + 255) / 256), 256>>>(b, out, N);
}

// round 12
// speedup vs baseline: 2.3319x; 1.0727x over previous
#include <cuda_runtime.h>

#define LDIM 128
#define NMAX 50000
#define EMAX 800000
#define SCAN_BLK 1024
#define NCHUNK_MAX ((NMAX + SCAN_BLK - 1) / SCAN_BLK)

// Scratch (allocation-free rule: __device__ globals)
__device__ __align__(16) float g_xw[(size_t)NMAX * LDIM]; // x@W (UNscaled)
__device__ float g_dinv[NMAX];   // rsqrt(deg+1)
__device__ int g_cnt[NMAX];      // in-degree (excl. self loop)
__device__ int g_off[NMAX];      // CSR offsets
__device__ int g_cur[NMAX];      // fill cursors (init = g_off)
__device__ int g_adj[EMAX];      // src indices bucketed by dst
__device__ volatile int g_look[NCHUNK_MAX]; // lookback words: 0=empty, agg+1
__device__ unsigned g_wbhi[64 * LDIM];  // W bf16 hi, packed k-pairs: [kpair][n]
__device__ unsigned g_wblo[64 * LDIM];  // W bf16 lo residuals

// ---- bf16 pack/split helpers ------------------------------------------------
__device__ __forceinline__ unsigned packbf(float x, float y) {
    unsigned r;
    asm("cvt.rn.bf16x2.f32 %0, %1, %2;" : "=r"(r) : "f"(y), "f"(x));
    return r;
}
__device__ __forceinline__ float bf_lo(unsigned r) { return __uint_as_float(r << 16); }
__device__ __forceinline__ float bf_hi(unsigned r) { return __uint_as_float(r & 0xFFFF0000u); }

__device__ __forceinline__ void split_bf(float x, float y, unsigned& hi, unsigned& lo) {
    hi = packbf(x, y);
    lo = packbf(x - bf_lo(hi), y - bf_hi(hi));
}

// ---------------------------------------------------------------------------
// K0: zero counters + lookback words
// ---------------------------------------------------------------------------
__global__ void zero_kernel(int N, int nchunk) {
    int i = blockIdx.x * blockDim.x + threadIdx.x;
    if (i < N) g_cnt[i] = 0;
    if (i < nchunk) g_look[i] = 0;
}

// ---------------------------------------------------------------------------
// K1: histogram of dst
// ---------------------------------------------------------------------------
__global__ void hist_kernel(const int* __restrict__ dst, int E) {
    int e = blockIdx.x * blockDim.x + threadIdx.x;
    if (e < E) atomicAdd(&g_cnt[dst[e]], 1);
}

// ---------------------------------------------------------------------------
// K1b: one-shot W -> packed bf16 hi/lo split, k-pair layout [kpair][n]
// (side stream: independent of edges)
// ---------------------------------------------------------------------------
__global__ void wsplit_kernel(const float* __restrict__ W) {
    int i = blockIdx.x * blockDim.x + threadIdx.x;
    if (i < 64 * LDIM) {
        int kp = i >> 7, n = i & 127;
        float v0 = W[(2 * kp) * LDIM + n];
        float v1 = W[(2 * kp + 1) * LDIM + n];
        unsigned hi, lo;
        split_bf(v0, v1, hi, lo);
        g_wbhi[i] = hi;
        g_wblo[i] = lo;
    }
}

// ---------------------------------------------------------------------------
// K2: decoupled-lookback exclusive scan; also emits g_dinv
// ---------------------------------------------------------------------------
__global__ __launch_bounds__(SCAN_BLK) void scan_lookback_kernel(int N) {
    __shared__ int warpsum[32];
    __shared__ int s_prefix;
    int t = threadIdx.x, lane = t & 31, wid = t >> 5;
    int bid = blockIdx.x;
    int gid = bid * SCAN_BLK + t;
    int v = (gid < N) ? g_cnt[gid] : 0;

    int x = v;
    #pragma unroll
    for (int off = 1; off < 32; off <<= 1) {
        int y = __shfl_up_sync(0xFFFFFFFFu, x, off);
        if (lane >= off) x += y;
    }
    if (lane == 31) warpsum[wid] = x;
    __syncthreads();
    if (wid == 0) {
        int w = warpsum[lane];
        #pragma unroll
        for (int off = 1; off < 32; off <<= 1) {
            int y = __shfl_up_sync(0xFFFFFFFFu, w, off);
            if (lane >= off) w += y;
        }
        warpsum[lane] = w;
    }
    __syncthreads();
    int warp_prefix = (wid == 0) ? 0 : warpsum[wid - 1];
    int block_total = warpsum[31];

    if (t == 0) g_look[bid] = block_total + 1;

    if (wid == 0) {
        int acc = 0;
        for (int base = 0; base < bid; base += 32) {
            int j = base + lane;
            int val = 0;
            if (j < bid) {
                do { val = g_look[j]; } while (val == 0);
                val -= 1;
            }
            #pragma unroll
            for (int off = 16; off > 0; off >>= 1)
                val += __shfl_xor_sync(0xFFFFFFFFu, val, off);
            acc += val;
        }
        if (lane == 0) s_prefix = acc;
    }
    __syncthreads();

    int o = s_prefix + warp_prefix + x - v;
    if (gid < N) {
        g_off[gid] = o;
        g_cur[gid] = o;
        g_dinv[gid] = rsqrtf((float)(v + 1));
    }
}

// ---------------------------------------------------------------------------
// K3: bucket fill
// ---------------------------------------------------------------------------
__global__ void fill_kernel(const int* __restrict__ src,
                            const int* __restrict__ dst, int E) {
    int e = blockIdx.x * blockDim.x + threadIdx.x;
    if (e >= E) return;
    int d = dst[e];
    int pos = atomicAdd(&g_cur[d], 1);
    g_adj[pos] = src[e];
}

// ---------------------------------------------------------------------------
// K4: bf16 m16n8k16 GEMM, 2xBF16 split. UNscaled output -> no g_cnt dep.
// ---------------------------------------------------------------------------
#define A_STRIDE 68
#define BP_STRIDE 136
#define OFF_A 0
#define OFF_BH (128 * A_STRIDE)
#define OFF_BL (128 * A_STRIDE + 32 * BP_STRIDE)
#define GEMM_SMEM ((128 * A_STRIDE + 2 * 32 * BP_STRIDE) * 4)

__device__ __forceinline__ void mma_bf16(float* c,
                                         unsigned a0, unsigned a1,
                                         unsigned a2, unsigned a3,
                                         unsigned b0, unsigned b1) {
    asm volatile(
        "mma.sync.aligned.m16n8k16.row.col.f32.bf16.bf16.f32 "
        "{%0,%1,%2,%3}, {%4,%5,%6,%7}, {%8,%9}, {%0,%1,%2,%3};"
        : "+f"(c[0]), "+f"(c[1]), "+f"(c[2]), "+f"(c[3])
        : "r"(a0), "r"(a1), "r"(a2), "r"(a3), "r"(b0), "r"(b1));
}

__global__ __launch_bounds__(512, 2) void gemm_mma_kernel(
    const float* __restrict__ x, int N)
{
    extern __shared__ unsigned smu[];
    float* smf = (float*)smu;
    const int tid = threadIdx.x;
    const int wid = tid >> 5;
    const int lane = tid & 31;
    const int g = lane >> 2;
    const int t4 = lane & 3;
    const int block_row = blockIdx.x * 128;
    const int wr0 = (wid >> 1) * 16;
    const int wc0 = (wid & 1) * 64;

    float acc[8][4];
    #pragma unroll
    for (int nt = 0; nt < 8; nt++)
        #pragma unroll
        for (int j = 0; j < 4; j++) acc[nt][j] = 0.0f;

    #pragma unroll 1
    for (int stage = 0; stage < 2; stage++) {
        int k0 = stage * 64;
        int kp0 = stage * 32;
        if (stage) __syncthreads();

        for (int i = tid; i < 128 * 64; i += 512) {
            int r = i >> 6, c = i & 63;
            int grow = block_row + r;
            float v = (grow < N) ? __ldg(&x[(size_t)grow * LDIM + k0 + c]) : 0.0f;
            smf[OFF_A + r * A_STRIDE + c] = v;
        }
        for (int i = tid; i < 32 * 128; i += 512) {
            int kp = i >> 7, n = i & 127;
            smu[OFF_BH + kp * BP_STRIDE + n] = g_wbhi[(kp0 + kp) * LDIM + n];
            smu[OFF_BL + kp * BP_STRIDE + n] = g_wblo[(kp0 + kp) * LDIM + n];
        }
        __syncthreads();

        #pragma unroll
        for (int ks = 0; ks < 4; ks++) {
            const float2* A2r0 = (const float2*)(smf + OFF_A) + (wr0 + g) * (A_STRIDE / 2) + ks * 8;
            const float2* A2r1 = A2r0 + 8 * (A_STRIDE / 2);
            float2 f0 = A2r0[t4];
            float2 f1 = A2r1[t4];
            float2 f2 = A2r0[t4 + 4];
            float2 f3 = A2r1[t4 + 4];
            unsigned ah0, al0, ah1, al1, ah2, al2, ah3, al3;
            split_bf(f0.x, f0.y, ah0, al0);
            split_bf(f1.x, f1.y, ah1, al1);
            split_bf(f2.x, f2.y, ah2, al2);
            split_bf(f3.x, f3.y, ah3, al3);

            const unsigned* Bh = smu + OFF_BH + (ks * 8 + t4) * BP_STRIDE + wc0 + g;
            const unsigned* Bl = smu + OFF_BL + (ks * 8 + t4) * BP_STRIDE + wc0 + g;
            #pragma unroll
            for (int nt = 0; nt < 8; nt++) {
                unsigned bh0 = Bh[nt * 8];
                unsigned bh1 = Bh[4 * BP_STRIDE + nt * 8];
                unsigned bl0 = Bl[nt * 8];
                unsigned bl1 = Bl[4 * BP_STRIDE + nt * 8];
                mma_bf16(acc[nt], ah0, ah1, ah2, ah3, bh0, bh1);
                mma_bf16(acc[nt], ah0, ah1, ah2, ah3, bl0, bl1);
                mma_bf16(acc[nt], al0, al1, al2, al3, bh0, bh1);
            }
        }
    }

    int row0 = block_row + wr0 + g;
    int row1 = row0 + 8;

    #pragma unroll
    for (int nt = 0; nt < 8; nt++) {
        int col = wc0 + nt * 8 + 2 * t4;
        if (row0 < N) {
            float2 o = make_float2(acc[nt][0], acc[nt][1]);
            *(float2*)&g_xw[(size_t)row0 * LDIM + col] = o;
        }
        if (row1 < N) {
            float2 o = make_float2(acc[nt][2], acc[nt][3]);
            *(float2*)&g_xw[(size_t)row1 * LDIM + col] = o;
        }
    }
}

// ---------------------------------------------------------------------------
// K5: one warp per node; per-neighbor dinv[src] scaling (FMA), fused softmax.
// ---------------------------------------------------------------------------
__global__ void gather_finalize_kernel(const float* __restrict__ b,
                                       float* __restrict__ out, int N)
{
    int gw = (blockIdx.x * blockDim.x + threadIdx.x) >> 5;
    int lane = threadIdx.x & 31;
    if (gw >= N) return;

    int start = g_off[gw];
    int len   = g_cnt[gw];
    const size_t lbase = (size_t)lane * 4;

    float4 acc = make_float4(0.f, 0.f, 0.f, 0.f);

    for (int base = 0; base < len; base += 32) {
        int idx = 0; float dv = 0.0f;
        if (base + lane < len) {
            idx = __ldg(&g_adj[start + base + lane]);
            dv = __ldg(&g_dinv[idx]);
        }
        int m = min(32, len - base);
        int j = 0;
        for (; j + 8 <= m; j += 8) {
            int s0 = __shfl_sync(0xFFFFFFFFu, idx, j + 0);
            int s1 = __shfl_sync(0xFFFFFFFFu, idx, j + 1);
            int s2 = __shfl_sync(0xFFFFFFFFu, idx, j + 2);
            int s3 = __shfl_sync(0xFFFFFFFFu, idx, j + 3);
            int s4 = __shfl_sync(0xFFFFFFFFu, idx, j + 4);
            int s5 = __shfl_sync(0xFFFFFFFFu, idx, j + 5);
            int s6 = __shfl_sync(0xFFFFFFFFu, idx, j + 6);
            int s7 = __shfl_sync(0xFFFFFFFFu, idx, j + 7);
            float w0 = __shfl_sync(0xFFFFFFFFu, dv, j + 0);
            float w1 = __shfl_sync(0xFFFFFFFFu, dv, j + 1);
            float w2 = __shfl_sync(0xFFFFFFFFu, dv, j + 2);
            float w3 = __shfl_sync(0xFFFFFFFFu, dv, j + 3);
            float w4 = __shfl_sync(0xFFFFFFFFu, dv, j + 4);
            float w5 = __shfl_sync(0xFFFFFFFFu, dv, j + 5);
            float w6 = __shfl_sync(0xFFFFFFFFu, dv, j + 6);
            float w7 = __shfl_sync(0xFFFFFFFFu, dv, j + 7);
            float4 v0 = *(const float4*)&g_xw[(size_t)s0 * LDIM + lbase];
            float4 v1 = *(const float4*)&g_xw[(size_t)s1 * LDIM + lbase];
            float4 v2 = *(const float4*)&g_xw[(size_t)s2 * LDIM + lbase];
            float4 v3 = *(const float4*)&g_xw[(size_t)s3 * LDIM + lbase];
            float4 v4 = *(const float4*)&g_xw[(size_t)s4 * LDIM + lbase];
            float4 v5 = *(const float4*)&g_xw[(size_t)s5 * LDIM + lbase];
            float4 v6 = *(const float4*)&g_xw[(size_t)s6 * LDIM + lbase];
            float4 v7 = *(const float4*)&g_xw[(size_t)s7 * LDIM + lbase];
            acc.x = fmaf(w0, v0.x, fmaf(w1, v1.x, fmaf(w2, v2.x, fmaf(w3, v3.x,
                    fmaf(w4, v4.x, fmaf(w5, v5.x, fmaf(w6, v6.x, fmaf(w7, v7.x, acc.x))))))));
            acc.y = fmaf(w0, v0.y, fmaf(w1, v1.y, fmaf(w2, v2.y, fmaf(w3, v3.y,
                    fmaf(w4, v4.y, fmaf(w5, v5.y, fmaf(w6, v6.y, fmaf(w7, v7.y, acc.y))))))));
            acc.z = fmaf(w0, v0.z, fmaf(w1, v1.z, fmaf(w2, v2.z, fmaf(w3, v3.z,
                    fmaf(w4, v4.z, fmaf(w5, v5.z, fmaf(w6, v6.z, fmaf(w7, v7.z, acc.z))))))));
            acc.w = fmaf(w0, v0.w, fmaf(w1, v1.w, fmaf(w2, v2.w, fmaf(w3, v3.w,
                    fmaf(w4, v4.w, fmaf(w5, v5.w, fmaf(w6, v6.w, fmaf(w7, v7.w, acc.w))))))));
        }
        for (; j < m; j++) {
            int s = __shfl_sync(0xFFFFFFFFu, idx, j);
            float ws = __shfl_sync(0xFFFFFFFFu, dv, j);
            float4 v = *(const float4*)&g_xw[(size_t)s * LDIM + lbase];
            acc.x = fmaf(ws, v.x, acc.x);
            acc.y = fmaf(ws, v.y, acc.y);
            acc.z = fmaf(ws, v.z, acc.z);
            acc.w = fmaf(ws, v.w, acc.w);
        }
    }

    // self loop (dinv_d * xw_d) + normalize by dinv_d + bias + relu
    float dinv = __ldg(&g_dinv[gw]);
    float4 w  = *(const float4*)&g_xw[(size_t)gw * LDIM + lbase];
    float4 bb = *(const float4*)&b[lbase];

    float v0 = fmaxf(fmaf(dinv, fmaf(dinv, w.x, acc.x), bb.x), 0.0f);
    float v1 = fmaxf(fmaf(dinv, fmaf(dinv, w.y, acc.y), bb.y), 0.0f);
    float v2 = fmaxf(fmaf(dinv, fmaf(dinv, w.z, acc.z), bb.z), 0.0f);
    float v3 = fmaxf(fmaf(dinv, fmaf(dinv, w.w, acc.w), bb.w), 0.0f);

    float m = fmaxf(fmaxf(v0, v1), fmaxf(v2, v3));
    #pragma unroll
    for (int off = 16; off > 0; off >>= 1)
        m = fmaxf(m, __shfl_xor_sync(0xFFFFFFFFu, m, off));

    float e0 = __expf(v0 - m);
    float e1 = __expf(v1 - m);
    float e2 = __expf(v2 - m);
    float e3 = __expf(v3 - m);
    float s = e0 + e1 + e2 + e3;
    #pragma unroll
    for (int off = 16; off > 0; off >>= 1)
        s += __shfl_xor_sync(0xFFFFFFFFu, s, off);

    float inv = __frcp_rn(s);
    float4 o;
    o.x = e0 * inv; o.y = e1 * inv; o.z = e2 * inv; o.w = e3 * inv;
    *(float4*)&out[(size_t)gw * LDIM + lbase] = o;
}

// ---------------------------------------------------------------------------
extern "C" void kernel_launch(void* const* d_in, const int* in_sizes, int n_in,
                              void* d_out, int out_size)
{
    const float* x  = (const float*)d_in[0];
    const int*   ei = (const int*)d_in[1];
    const float* W  = (const float*)d_in[2];
    const float* b  = (const float*)d_in[3];
    float* out = (float*)d_out;

    int N = in_sizes[0] / LDIM;   // 50000
    int E = in_sizes[1] / 2;      // 800000
    const int* src = ei;
    const int* dst = ei + E;
    int nchunk = (N + SCAN_BLK - 1) / SCAN_BLK;

    // Fork-join: side stream runs wsplit+GEMM concurrently with CSR build.
    // Handles are created per call and intentionally not destroyed (host-side
    // handles only; destruction during active capture is illegal).
    cudaStream_t s2;
    cudaStreamCreateWithFlags(&s2, cudaStreamNonBlocking);
    cudaEvent_t evRoot, evGemm;
    cudaEventCreateWithFlags(&evRoot, cudaEventDisableTiming);
    cudaEventCreateWithFlags(&evGemm, cudaEventDisableTiming);

    cudaEventRecord(evRoot, 0);
    cudaStreamWaitEvent(s2, evRoot, 0);

    // side stream: W split + GEMM (independent of edge data)
    wsplit_kernel<<<(64 * LDIM + 255) / 256, 256, 0, s2>>>(W);
    cudaFuncSetAttribute(gemm_mma_kernel,
                         cudaFuncAttributeMaxDynamicSharedMemorySize, GEMM_SMEM);
    gemm_mma_kernel<<<(N + 127) / 128, 512, GEMM_SMEM, s2>>>(x, N);
    cudaEventRecord(evGemm, s2);

    // main stream: CSR build
    zero_kernel<<<(N + 255) / 256, 256>>>(N, nchunk);
    hist_kernel<<<(E + 255) / 256, 256>>>(dst, E);
    scan_lookback_kernel<<<nchunk, SCAN_BLK>>>(N);
    fill_kernel<<<(E + 255) / 256, 256>>>(src, dst, E);

    // join, then gather
    cudaStreamWaitEvent(0, evGemm, 0);
    long long gthreads = (long long)N * 32;
    gather_finalize_kernel<<<(int)((gthreads + 255) / 256), 256>>>(b, out, N);
}

// round 13
// speedup vs baseline: 2.3515x; 1.0084x over previous
#include <cuda_runtime.h>

#define LDIM 128
#define NMAX 50000
#define EMAX 800000
#define SCAN_BLK 1024
#define NCHUNK_MAX ((NMAX + SCAN_BLK - 1) / SCAN_BLK)

// Scratch (allocation-free rule: __device__ globals)
__device__ __align__(16) float g_xw[(size_t)NMAX * LDIM]; // x@W (UNscaled)
__device__ float g_dinv[NMAX];
__device__ int g_cnt[NMAX];
__device__ int g_off[NMAX];
__device__ int g_cur[NMAX];
__device__ int g_adj[EMAX];
__device__ volatile int g_look[NCHUNK_MAX];
__device__ unsigned g_wbhi[64 * LDIM];  // W bf16 hi, packed k-pairs [kpair][n]
__device__ unsigned g_wblo[64 * LDIM];  // W bf16 lo residuals

// ---- bf16 pack/split helpers ------------------------------------------------
__device__ __forceinline__ unsigned packbf(float x, float y) {
    unsigned r;
    asm("cvt.rn.bf16x2.f32 %0, %1, %2;" : "=r"(r) : "f"(y), "f"(x));
    return r;
}
__device__ __forceinline__ float bf_lo(unsigned r) { return __uint_as_float(r << 16); }
__device__ __forceinline__ float bf_hi(unsigned r) { return __uint_as_float(r & 0xFFFF0000u); }
__device__ __forceinline__ void split_bf(float x, float y, unsigned& hi, unsigned& lo) {
    hi = packbf(x, y);
    lo = packbf(x - bf_lo(hi), y - bf_hi(hi));
}

// ---------------------------------------------------------------------------
// K0-K3: CSR build (unchanged)
// ---------------------------------------------------------------------------
__global__ void zero_kernel(int N, int nchunk) {
    int i = blockIdx.x * blockDim.x + threadIdx.x;
    if (i < N) g_cnt[i] = 0;
    if (i < nchunk) g_look[i] = 0;
}

__global__ void hist_kernel(const int* __restrict__ dst, int E) {
    int e = blockIdx.x * blockDim.x + threadIdx.x;
    if (e < E) atomicAdd(&g_cnt[dst[e]], 1);
}

__global__ void wsplit_kernel(const float* __restrict__ W) {
    int i = blockIdx.x * blockDim.x + threadIdx.x;
    if (i < 64 * LDIM) {
        int kp = i >> 7, n = i & 127;
        float v0 = W[(2 * kp) * LDIM + n];
        float v1 = W[(2 * kp + 1) * LDIM + n];
        unsigned hi, lo;
        split_bf(v0, v1, hi, lo);
        g_wbhi[i] = hi;
        g_wblo[i] = lo;
    }
}

__global__ __launch_bounds__(SCAN_BLK) void scan_lookback_kernel(int N) {
    __shared__ int warpsum[32];
    __shared__ int s_prefix;
    int t = threadIdx.x, lane = t & 31, wid = t >> 5;
    int bid = blockIdx.x;
    int gid = bid * SCAN_BLK + t;
    int v = (gid < N) ? g_cnt[gid] : 0;

    int x = v;
    #pragma unroll
    for (int off = 1; off < 32; off <<= 1) {
        int y = __shfl_up_sync(0xFFFFFFFFu, x, off);
        if (lane >= off) x += y;
    }
    if (lane == 31) warpsum[wid] = x;
    __syncthreads();
    if (wid == 0) {
        int w = warpsum[lane];
        #pragma unroll
        for (int off = 1; off < 32; off <<= 1) {
            int y = __shfl_up_sync(0xFFFFFFFFu, w, off);
            if (lane >= off) w += y;
        }
        warpsum[lane] = w;
    }
    __syncthreads();
    int warp_prefix = (wid == 0) ? 0 : warpsum[wid - 1];
    int block_total = warpsum[31];

    if (t == 0) g_look[bid] = block_total + 1;

    if (wid == 0) {
        int acc = 0;
        for (int base = 0; base < bid; base += 32) {
            int j = base + lane;
            int val = 0;
            if (j < bid) {
                do { val = g_look[j]; } while (val == 0);
                val -= 1;
            }
            #pragma unroll
            for (int off = 16; off > 0; off >>= 1)
                val += __shfl_xor_sync(0xFFFFFFFFu, val, off);
            acc += val;
        }
        if (lane == 0) s_prefix = acc;
    }
    __syncthreads();

    int o = s_prefix + warp_prefix + x - v;
    if (gid < N) {
        g_off[gid] = o;
        g_cur[gid] = o;
        g_dinv[gid] = rsqrtf((float)(v + 1));
    }
}

__global__ void fill_kernel(const int* __restrict__ src,
                            const int* __restrict__ dst, int E) {
    int e = blockIdx.x * blockDim.x + threadIdx.x;
    if (e >= E) return;
    int d = dst[e];
    int pos = atomicAdd(&g_cur[d], 1);
    g_adj[pos] = src[e];
}

// ---------------------------------------------------------------------------
// K4: bf16 m16n8k16 GEMM, 2xBF16 split, cp.async double-buffered 4-stage pipe.
// ---------------------------------------------------------------------------
#define AST 36                      // A stride in floats (32 data + 4 pad)
#define BST 136                     // B stride in words
#define A_WORDS (128 * AST)         // 4608
#define B_HI_WORDS (16 * BST)       // 2176
#define B_BUF_WORDS (2 * B_HI_WORDS)
#define OFF_A(b)  ((b) * A_WORDS)
#define OFF_BH(b) (2 * A_WORDS + (b) * B_BUF_WORDS)
#define OFF_BL(b) (OFF_BH(b) + B_HI_WORDS)
#define GEMM_SMEM ((2 * A_WORDS + 2 * B_BUF_WORDS) * 4)   // 71680 B

__device__ __forceinline__ void cp16(unsigned saddr, const void* g, unsigned srcsz) {
    asm volatile("cp.async.ca.shared.global [%0], [%1], 16, %2;"
                 :: "r"(saddr), "l"(g), "r"(srcsz) : "memory");
}

__device__ __forceinline__ void mma_bf16(float* c,
                                         unsigned a0, unsigned a1,
                                         unsigned a2, unsigned a3,
                                         unsigned b0, unsigned b1) {
    asm volatile(
        "mma.sync.aligned.m16n8k16.row.col.f32.bf16.bf16.f32 "
        "{%0,%1,%2,%3}, {%4,%5,%6,%7}, {%8,%9}, {%0,%1,%2,%3};"
        : "+f"(c[0]), "+f"(c[1]), "+f"(c[2]), "+f"(c[3])
        : "r"(a0), "r"(a1), "r"(a2), "r"(a3), "r"(b0), "r"(b1));
}

__global__ __launch_bounds__(512, 2) void gemm_mma_kernel(
    const float* __restrict__ x, int N)
{
    extern __shared__ unsigned smu[];
    float* smf = (float*)smu;
    unsigned sbase = (unsigned)__cvta_generic_to_shared(smu);
    const int tid = threadIdx.x;
    const int wid = tid >> 5;
    const int lane = tid & 31;
    const int g = lane >> 2;
    const int t4 = lane & 3;
    const int block_row = blockIdx.x * 128;
    const int wr0 = (wid >> 1) * 16;
    const int wc0 = (wid & 1) * 64;

    float acc[8][4];
    #pragma unroll
    for (int nt = 0; nt < 8; nt++)
        #pragma unroll
        for (int j = 0; j < 4; j++) acc[nt][j] = 0.0f;

    // ---- prefetch helper (inlined twice via lambda-style macro loop) ----
    auto prefetch = [&](int s, int buf) {
        int k0 = s * 32, kp0 = s * 16;
        // A: 128 rows x 32 floats = 1024 x 16B chunks
        for (int c = tid; c < 1024; c += 512) {
            int r = c >> 3, cj = c & 7;
            int grow = block_row + r;
            unsigned sa = sbase + (unsigned)(OFF_A(buf) + r * AST + cj * 4) * 4u;
            int crow = grow < N ? grow : (N - 1);
            const float* gp = x + (size_t)crow * LDIM + k0 + cj * 4;
            cp16(sa, gp, grow < N ? 16u : 0u);
        }
        // B: hi + lo, 16 kpair rows x 128 words = 512 chunks each
        for (int c = tid; c < 1024; c += 512) {
            int half = c >> 9;
            int cc = c & 511;
            int kp = cc >> 5, cj = cc & 31;
            unsigned off = half ? (unsigned)OFF_BL(buf) : (unsigned)OFF_BH(buf);
            unsigned sa = sbase + (off + (unsigned)(kp * BST + cj * 4)) * 4u;
            const unsigned* gp = (half ? g_wblo : g_wbhi) + (kp0 + kp) * LDIM + cj * 4;
            cp16(sa, gp, 16u);
        }
    };

    prefetch(0, 0);
    asm volatile("cp.async.commit_group;" ::: "memory");

    #pragma unroll 1
    for (int s = 0; s < 4; s++) {
        int buf = s & 1;
        if (s < 3) {
            prefetch(s + 1, buf ^ 1);
            asm volatile("cp.async.commit_group;" ::: "memory");
            asm volatile("cp.async.wait_group 1;" ::: "memory");
        } else {
            asm volatile("cp.async.wait_group 0;" ::: "memory");
        }
        __syncthreads();

        #pragma unroll
        for (int ks = 0; ks < 2; ks++) {
            const float2* A2r0 = (const float2*)(smf + OFF_A(buf)) + (wr0 + g) * (AST / 2) + ks * 8;
            const float2* A2r1 = A2r0 + 8 * (AST / 2);
            float2 f0 = A2r0[t4];
            float2 f1 = A2r1[t4];
            float2 f2 = A2r0[t4 + 4];
            float2 f3 = A2r1[t4 + 4];
            unsigned ah0, al0, ah1, al1, ah2, al2, ah3, al3;
            split_bf(f0.x, f0.y, ah0, al0);
            split_bf(f1.x, f1.y, ah1, al1);
            split_bf(f2.x, f2.y, ah2, al2);
            split_bf(f3.x, f3.y, ah3, al3);

            const unsigned* Bh = smu + OFF_BH(buf) + (ks * 8 + t4) * BST + wc0 + g;
            const unsigned* Bl = smu + OFF_BL(buf) + (ks * 8 + t4) * BST + wc0 + g;
            #pragma unroll
            for (int nt = 0; nt < 8; nt++) {
                unsigned bh0 = Bh[nt * 8];
                unsigned bh1 = Bh[4 * BST + nt * 8];
                unsigned bl0 = Bl[nt * 8];
                unsigned bl1 = Bl[4 * BST + nt * 8];
                mma_bf16(acc[nt], ah0, ah1, ah2, ah3, bh0, bh1);
                mma_bf16(acc[nt], ah0, ah1, ah2, ah3, bl0, bl1);
                mma_bf16(acc[nt], al0, al1, al2, al3, bh0, bh1);
            }
        }
        __syncthreads();   // compute done before next prefetch overwrites buf^1
    }

    int row0 = block_row + wr0 + g;
    int row1 = row0 + 8;

    #pragma unroll
    for (int nt = 0; nt < 8; nt++) {
        int col = wc0 + nt * 8 + 2 * t4;
        if (row0 < N) {
            float2 o = make_float2(acc[nt][0], acc[nt][1]);
            *(float2*)&g_xw[(size_t)row0 * LDIM + col] = o;
        }
        if (row1 < N) {
            float2 o = make_float2(acc[nt][2], acc[nt][3]);
            *(float2*)&g_xw[(size_t)row1 * LDIM + col] = o;
        }
    }
}

// ---------------------------------------------------------------------------
// K5: gather + finalize (unchanged from R12)
// ---------------------------------------------------------------------------
__global__ void gather_finalize_kernel(const float* __restrict__ b,
                                       float* __restrict__ out, int N)
{
    int gw = (blockIdx.x * blockDim.x + threadIdx.x) >> 5;
    int lane = threadIdx.x & 31;
    if (gw >= N) return;

    int start = g_off[gw];
    int len   = g_cnt[gw];
    const size_t lbase = (size_t)lane * 4;

    float4 acc = make_float4(0.f, 0.f, 0.f, 0.f);

    for (int base = 0; base < len; base += 32) {
        int idx = 0; float dv = 0.0f;
        if (base + lane < len) {
            idx = __ldg(&g_adj[start + base + lane]);
            dv = __ldg(&g_dinv[idx]);
        }
        int m = min(32, len - base);
        int j = 0;
        for (; j + 8 <= m; j += 8) {
            int s0 = __shfl_sync(0xFFFFFFFFu, idx, j + 0);
            int s1 = __shfl_sync(0xFFFFFFFFu, idx, j + 1);
            int s2 = __shfl_sync(0xFFFFFFFFu, idx, j + 2);
            int s3 = __shfl_sync(0xFFFFFFFFu, idx, j + 3);
            int s4 = __shfl_sync(0xFFFFFFFFu, idx, j + 4);
            int s5 = __shfl_sync(0xFFFFFFFFu, idx, j + 5);
            int s6 = __shfl_sync(0xFFFFFFFFu, idx, j + 6);
            int s7 = __shfl_sync(0xFFFFFFFFu, idx, j + 7);
            float w0 = __shfl_sync(0xFFFFFFFFu, dv, j + 0);
            float w1 = __shfl_sync(0xFFFFFFFFu, dv, j + 1);
            float w2 = __shfl_sync(0xFFFFFFFFu, dv, j + 2);
            float w3 = __shfl_sync(0xFFFFFFFFu, dv, j + 3);
            float w4 = __shfl_sync(0xFFFFFFFFu, dv, j + 4);
            float w5 = __shfl_sync(0xFFFFFFFFu, dv, j + 5);
            float w6 = __shfl_sync(0xFFFFFFFFu, dv, j + 6);
            float w7 = __shfl_sync(0xFFFFFFFFu, dv, j + 7);
            float4 v0 = *(const float4*)&g_xw[(size_t)s0 * LDIM + lbase];
            float4 v1 = *(const float4*)&g_xw[(size_t)s1 * LDIM + lbase];
            float4 v2 = *(const float4*)&g_xw[(size_t)s2 * LDIM + lbase];
            float4 v3 = *(const float4*)&g_xw[(size_t)s3 * LDIM + lbase];
            float4 v4 = *(const float4*)&g_xw[(size_t)s4 * LDIM + lbase];
            float4 v5 = *(const float4*)&g_xw[(size_t)s5 * LDIM + lbase];
            float4 v6 = *(const float4*)&g_xw[(size_t)s6 * LDIM + lbase];
            float4 v7 = *(const float4*)&g_xw[(size_t)s7 * LDIM + lbase];
            acc.x = fmaf(w0, v0.x, fmaf(w1, v1.x, fmaf(w2, v2.x, fmaf(w3, v3.x,
                    fmaf(w4, v4.x, fmaf(w5, v5.x, fmaf(w6, v6.x, fmaf(w7, v7.x, acc.x))))))));
            acc.y = fmaf(w0, v0.y, fmaf(w1, v1.y, fmaf(w2, v2.y, fmaf(w3, v3.y,
                    fmaf(w4, v4.y, fmaf(w5, v5.y, fmaf(w6, v6.y, fmaf(w7, v7.y, acc.y))))))));
            acc.z = fmaf(w0, v0.z, fmaf(w1, v1.z, fmaf(w2, v2.z, fmaf(w3, v3.z,
                    fmaf(w4, v4.z, fmaf(w5, v5.z, fmaf(w6, v6.z, fmaf(w7, v7.z, acc.z))))))));
            acc.w = fmaf(w0, v0.w, fmaf(w1, v1.w, fmaf(w2, v2.w, fmaf(w3, v3.w,
                    fmaf(w4, v4.w, fmaf(w5, v5.w, fmaf(w6, v6.w, fmaf(w7, v7.w, acc.w))))))));
        }
        for (; j < m; j++) {
            int s = __shfl_sync(0xFFFFFFFFu, idx, j);
            float ws = __shfl_sync(0xFFFFFFFFu, dv, j);
            float4 v = *(const float4*)&g_xw[(size_t)s * LDIM + lbase];
            acc.x = fmaf(ws, v.x, acc.x);
            acc.y = fmaf(ws, v.y, acc.y);
            acc.z = fmaf(ws, v.z, acc.z);
            acc.w = fmaf(ws, v.w, acc.w);
        }
    }

    float dinv = __ldg(&g_dinv[gw]);
    float4 w  = *(const float4*)&g_xw[(size_t)gw * LDIM + lbase];
    float4 bb = *(const float4*)&b[lbase];

    float v0 = fmaxf(fmaf(dinv, fmaf(dinv, w.x, acc.x), bb.x), 0.0f);
    float v1 = fmaxf(fmaf(dinv, fmaf(dinv, w.y, acc.y), bb.y), 0.0f);
    float v2 = fmaxf(fmaf(dinv, fmaf(dinv, w.z, acc.z), bb.z), 0.0f);
    float v3 = fmaxf(fmaf(dinv, fmaf(dinv, w.w, acc.w), bb.w), 0.0f);

    float m = fmaxf(fmaxf(v0, v1), fmaxf(v2, v3));
    #pragma unroll
    for (int off = 16; off > 0; off >>= 1)
        m = fmaxf(m, __shfl_xor_sync(0xFFFFFFFFu, m, off));

    float e0 = __expf(v0 - m);
    float e1 = __expf(v1 - m);
    float e2 = __expf(v2 - m);
    float e3 = __expf(v3 - m);
    float s = e0 + e1 + e2 + e3;
    #pragma unroll
    for (int off = 16; off > 0; off >>= 1)
        s += __shfl_xor_sync(0xFFFFFFFFu, s, off);

    float inv = __frcp_rn(s);
    float4 o;
    o.x = e0 * inv; o.y = e1 * inv; o.z = e2 * inv; o.w = e3 * inv;
    *(float4*)&out[(size_t)gw * LDIM + lbase] = o;
}

// ---------------------------------------------------------------------------
extern "C" void kernel_launch(void* const* d_in, const int* in_sizes, int n_in,
                              void* d_out, int out_size)
{
    const float* x  = (const float*)d_in[0];
    const int*   ei = (const int*)d_in[1];
    const float* W  = (const float*)d_in[2];
    const float* b  = (const float*)d_in[3];
    float* out = (float*)d_out;

    int N = in_sizes[0] / LDIM;   // 50000
    int E = in_sizes[1] / 2;      // 800000
    const int* src = ei;
    const int* dst = ei + E;
    int nchunk = (N + SCAN_BLK - 1) / SCAN_BLK;

    cudaStream_t s2;
    cudaStreamCreateWithFlags(&s2, cudaStreamNonBlocking);
    cudaEvent_t evRoot, evGemm;
    cudaEventCreateWithFlags(&evRoot, cudaEventDisableTiming);
    cudaEventCreateWithFlags(&evGemm, cudaEventDisableTiming);

    cudaEventRecord(evRoot, 0);
    cudaStreamWaitEvent(s2, evRoot, 0);

    // side stream: W split + GEMM
    wsplit_kernel<<<(64 * LDIM + 255) / 256, 256, 0, s2>>>(W);
    cudaFuncSetAttribute(gemm_mma_kernel,
                         cudaFuncAttributeMaxDynamicSharedMemorySize, GEMM_SMEM);
    gemm_mma_kernel<<<(N + 127) / 128, 512, GEMM_SMEM, s2>>>(x, N);
    cudaEventRecord(evGemm, s2);

    // main stream: CSR build
    zero_kernel<<<(N + 255) / 256, 256>>>(N, nchunk);
    hist_kernel<<<(E + 255) / 256, 256>>>(dst, E);
    scan_lookback_kernel<<<nchunk, SCAN_BLK>>>(N);
    fill_kernel<<<(E + 255) / 256, 256>>>(src, dst, E);

    cudaStreamWaitEvent(0, evGemm, 0);
    long long gthreads = (long long)N * 32;
    gather_finalize_kernel<<<(int)((gthreads + 255) / 256), 256>>>(b, out, N);
}

// round 14
// speedup vs baseline: 2.6088x; 1.1094x over previous
#include <cuda_runtime.h>
#include <cuda_fp16.h>

#define LDIM 128
#define NMAX 50000
#define EMAX 800000
#define SCAN_BLK 1024
#define NCHUNK_MAX ((NMAX + SCAN_BLK - 1) / SCAN_BLK)

// Scratch (allocation-free rule: __device__ globals)
__device__ __align__(16) __half2 g_xwh[(size_t)NMAX * 64]; // x@W as fp16 pairs
__device__ float g_dinv[NMAX];
__device__ int g_cnt[NMAX];
__device__ int g_off[NMAX];
__device__ int g_cur[NMAX];
__device__ int g_adj[EMAX];
__device__ volatile int g_look[NCHUNK_MAX];
__device__ unsigned g_wbhi[64 * LDIM];  // W bf16 hi, packed k-pairs [kpair][n]
__device__ unsigned g_wblo[64 * LDIM];  // W bf16 lo residuals

// ---- bf16 pack/split helpers ------------------------------------------------
__device__ __forceinline__ unsigned packbf(float x, float y) {
    unsigned r;
    asm("cvt.rn.bf16x2.f32 %0, %1, %2;" : "=r"(r) : "f"(y), "f"(x));
    return r;
}
__device__ __forceinline__ float bf_lo(unsigned r) { return __uint_as_float(r << 16); }
__device__ __forceinline__ float bf_hi(unsigned r) { return __uint_as_float(r & 0xFFFF0000u); }
__device__ __forceinline__ void split_bf(float x, float y, unsigned& hi, unsigned& lo) {
    hi = packbf(x, y);
    lo = packbf(x - bf_lo(hi), y - bf_hi(hi));
}

// ---------------------------------------------------------------------------
// K0-K3: CSR build (unchanged)
// ---------------------------------------------------------------------------
__global__ void zero_kernel(int N, int nchunk) {
    int i = blockIdx.x * blockDim.x + threadIdx.x;
    if (i < N) g_cnt[i] = 0;
    if (i < nchunk) g_look[i] = 0;
}

__global__ void hist_kernel(const int* __restrict__ dst, int E) {
    int e = blockIdx.x * blockDim.x + threadIdx.x;
    if (e < E) atomicAdd(&g_cnt[dst[e]], 1);
}

__global__ void wsplit_kernel(const float* __restrict__ W) {
    int i = blockIdx.x * blockDim.x + threadIdx.x;
    if (i < 64 * LDIM) {
        int kp = i >> 7, n = i & 127;
        float v0 = W[(2 * kp) * LDIM + n];
        float v1 = W[(2 * kp + 1) * LDIM + n];
        unsigned hi, lo;
        split_bf(v0, v1, hi, lo);
        g_wbhi[i] = hi;
        g_wblo[i] = lo;
    }
}

__global__ __launch_bounds__(SCAN_BLK) void scan_lookback_kernel(int N) {
    __shared__ int warpsum[32];
    __shared__ int s_prefix;
    int t = threadIdx.x, lane = t & 31, wid = t >> 5;
    int bid = blockIdx.x;
    int gid = bid * SCAN_BLK + t;
    int v = (gid < N) ? g_cnt[gid] : 0;

    int x = v;
    #pragma unroll
    for (int off = 1; off < 32; off <<= 1) {
        int y = __shfl_up_sync(0xFFFFFFFFu, x, off);
        if (lane >= off) x += y;
    }
    if (lane == 31) warpsum[wid] = x;
    __syncthreads();
    if (wid == 0) {
        int w = warpsum[lane];
        #pragma unroll
        for (int off = 1; off < 32; off <<= 1) {
            int y = __shfl_up_sync(0xFFFFFFFFu, w, off);
            if (lane >= off) w += y;
        }
        warpsum[lane] = w;
    }
    __syncthreads();
    int warp_prefix = (wid == 0) ? 0 : warpsum[wid - 1];
    int block_total = warpsum[31];

    if (t == 0) g_look[bid] = block_total + 1;

    if (wid == 0) {
        int acc = 0;
        for (int base = 0; base < bid; base += 32) {
            int j = base + lane;
            int val = 0;
            if (j < bid) {
                do { val = g_look[j]; } while (val == 0);
                val -= 1;
            }
            #pragma unroll
            for (int off = 16; off > 0; off >>= 1)
                val += __shfl_xor_sync(0xFFFFFFFFu, val, off);
            acc += val;
        }
        if (lane == 0) s_prefix = acc;
    }
    __syncthreads();

    int o = s_prefix + warp_prefix + x - v;
    if (gid < N) {
        g_off[gid] = o;
        g_cur[gid] = o;
        g_dinv[gid] = rsqrtf((float)(v + 1));
    }
}

__global__ void fill_kernel(const int* __restrict__ src,
                            const int* __restrict__ dst, int E) {
    int e = blockIdx.x * blockDim.x + threadIdx.x;
    if (e >= E) return;
    int d = dst[e];
    int pos = atomicAdd(&g_cur[d], 1);
    g_adj[pos] = src[e];
}

// ---------------------------------------------------------------------------
// K4: bf16 m16n8k16 GEMM, 2xBF16 split, cp.async pipe. fp16 output.
// ---------------------------------------------------------------------------
#define AST 36
#define BST 136
#define A_WORDS (128 * AST)
#define B_HI_WORDS (16 * BST)
#define B_BUF_WORDS (2 * B_HI_WORDS)
#define OFF_A(b)  ((b) * A_WORDS)
#define OFF_BH(b) (2 * A_WORDS + (b) * B_BUF_WORDS)
#define OFF_BL(b) (OFF_BH(b) + B_HI_WORDS)
#define GEMM_SMEM ((2 * A_WORDS + 2 * B_BUF_WORDS) * 4)

__device__ __forceinline__ void cp16(unsigned saddr, const void* g, unsigned srcsz) {
    asm volatile("cp.async.ca.shared.global [%0], [%1], 16, %2;"
                 :: "r"(saddr), "l"(g), "r"(srcsz) : "memory");
}

__device__ __forceinline__ void mma_bf16(float* c,
                                         unsigned a0, unsigned a1,
                                         unsigned a2, unsigned a3,
                                         unsigned b0, unsigned b1) {
    asm volatile(
        "mma.sync.aligned.m16n8k16.row.col.f32.bf16.bf16.f32 "
        "{%0,%1,%2,%3}, {%4,%5,%6,%7}, {%8,%9}, {%0,%1,%2,%3};"
        : "+f"(c[0]), "+f"(c[1]), "+f"(c[2]), "+f"(c[3])
        : "r"(a0), "r"(a1), "r"(a2), "r"(a3), "r"(b0), "r"(b1));
}

__global__ __launch_bounds__(512, 2) void gemm_mma_kernel(
    const float* __restrict__ x, int N)
{
    extern __shared__ unsigned smu[];
    float* smf = (float*)smu;
    unsigned sbase = (unsigned)__cvta_generic_to_shared(smu);
    const int tid = threadIdx.x;
    const int wid = tid >> 5;
    const int lane = tid & 31;
    const int g = lane >> 2;
    const int t4 = lane & 3;
    const int block_row = blockIdx.x * 128;
    const int wr0 = (wid >> 1) * 16;
    const int wc0 = (wid & 1) * 64;

    float acc[8][4];
    #pragma unroll
    for (int nt = 0; nt < 8; nt++)
        #pragma unroll
        for (int j = 0; j < 4; j++) acc[nt][j] = 0.0f;

    auto prefetch = [&](int s, int buf) {
        int k0 = s * 32, kp0 = s * 16;
        for (int c = tid; c < 1024; c += 512) {
            int r = c >> 3, cj = c & 7;
            int grow = block_row + r;
            unsigned sa = sbase + (unsigned)(OFF_A(buf) + r * AST + cj * 4) * 4u;
            int crow = grow < N ? grow : (N - 1);
            const float* gp = x + (size_t)crow * LDIM + k0 + cj * 4;
            cp16(sa, gp, grow < N ? 16u : 0u);
        }
        for (int c = tid; c < 1024; c += 512) {
            int half = c >> 9;
            int cc = c & 511;
            int kp = cc >> 5, cj = cc & 31;
            unsigned off = half ? (unsigned)OFF_BL(buf) : (unsigned)OFF_BH(buf);
            unsigned sa = sbase + (off + (unsigned)(kp * BST + cj * 4)) * 4u;
            const unsigned* gp = (half ? g_wblo : g_wbhi) + (kp0 + kp) * LDIM + cj * 4;
            cp16(sa, gp, 16u);
        }
    };

    prefetch(0, 0);
    asm volatile("cp.async.commit_group;" ::: "memory");

    #pragma unroll 1
    for (int s = 0; s < 4; s++) {
        int buf = s & 1;
        if (s < 3) {
            prefetch(s + 1, buf ^ 1);
            asm volatile("cp.async.commit_group;" ::: "memory");
            asm volatile("cp.async.wait_group 1;" ::: "memory");
        } else {
            asm volatile("cp.async.wait_group 0;" ::: "memory");
        }
        __syncthreads();

        #pragma unroll
        for (int ks = 0; ks < 2; ks++) {
            const float2* A2r0 = (const float2*)(smf + OFF_A(buf)) + (wr0 + g) * (AST / 2) + ks * 8;
            const float2* A2r1 = A2r0 + 8 * (AST / 2);
            float2 f0 = A2r0[t4];
            float2 f1 = A2r1[t4];
            float2 f2 = A2r0[t4 + 4];
            float2 f3 = A2r1[t4 + 4];
            unsigned ah0, al0, ah1, al1, ah2, al2, ah3, al3;
            split_bf(f0.x, f0.y, ah0, al0);
            split_bf(f1.x, f1.y, ah1, al1);
            split_bf(f2.x, f2.y, ah2, al2);
            split_bf(f3.x, f3.y, ah3, al3);

            const unsigned* Bh = smu + OFF_BH(buf) + (ks * 8 + t4) * BST + wc0 + g;
            const unsigned* Bl = smu + OFF_BL(buf) + (ks * 8 + t4) * BST + wc0 + g;
            #pragma unroll
            for (int nt = 0; nt < 8; nt++) {
                unsigned bh0 = Bh[nt * 8];
                unsigned bh1 = Bh[4 * BST + nt * 8];
                unsigned bl0 = Bl[nt * 8];
                unsigned bl1 = Bl[4 * BST + nt * 8];
                mma_bf16(acc[nt], ah0, ah1, ah2, ah3, bh0, bh1);
                mma_bf16(acc[nt], ah0, ah1, ah2, ah3, bl0, bl1);
                mma_bf16(acc[nt], al0, al1, al2, al3, bh0, bh1);
            }
        }
        __syncthreads();
    }

    int row0 = block_row + wr0 + g;
    int row1 = row0 + 8;

    #pragma unroll
    for (int nt = 0; nt < 8; nt++) {
        int cp2 = (wc0 >> 1) + nt * 4 + t4;   // half2 column index
        if (row0 < N)
            g_xwh[(size_t)row0 * 64 + cp2] = __floats2half2_rn(acc[nt][0], acc[nt][1]);
        if (row1 < N)
            g_xwh[(size_t)row1 * 64 + cp2] = __floats2half2_rn(acc[nt][2], acc[nt][3]);
    }
}

// ---------------------------------------------------------------------------
// K5: gather + finalize; fp16 feature reads (8B/lane), fp32 accumulate.
// ---------------------------------------------------------------------------
__global__ void gather_finalize_kernel(const float* __restrict__ b,
                                       float* __restrict__ out, int N)
{
    int gw = (blockIdx.x * blockDim.x + threadIdx.x) >> 5;
    int lane = threadIdx.x & 31;
    if (gw >= N) return;

    int start = g_off[gw];
    int len   = g_cnt[gw];
    const int h2base = lane * 2;   // 2 half2 = 4 cols per lane

    float4 acc = make_float4(0.f, 0.f, 0.f, 0.f);

    auto loadrow = [&](int s) -> float4 {
        const __half2* p = g_xwh + (size_t)s * 64 + h2base;
        __half2 h0 = __ldg(p);
        __half2 h1 = __ldg(p + 1);
        float2 a = __half22float2(h0);
        float2 c = __half22float2(h1);
        return make_float4(a.x, a.y, c.x, c.y);
    };

    for (int base = 0; base < len; base += 32) {
        int idx = 0; float dv = 0.0f;
        if (base + lane < len) {
            idx = __ldg(&g_adj[start + base + lane]);
            dv = __ldg(&g_dinv[idx]);
        }
        int m = min(32, len - base);
        int j = 0;
        for (; j + 8 <= m; j += 8) {
            int s0 = __shfl_sync(0xFFFFFFFFu, idx, j + 0);
            int s1 = __shfl_sync(0xFFFFFFFFu, idx, j + 1);
            int s2 = __shfl_sync(0xFFFFFFFFu, idx, j + 2);
            int s3 = __shfl_sync(0xFFFFFFFFu, idx, j + 3);
            int s4 = __shfl_sync(0xFFFFFFFFu, idx, j + 4);
            int s5 = __shfl_sync(0xFFFFFFFFu, idx, j + 5);
            int s6 = __shfl_sync(0xFFFFFFFFu, idx, j + 6);
            int s7 = __shfl_sync(0xFFFFFFFFu, idx, j + 7);
            float w0 = __shfl_sync(0xFFFFFFFFu, dv, j + 0);
            float w1 = __shfl_sync(0xFFFFFFFFu, dv, j + 1);
            float w2 = __shfl_sync(0xFFFFFFFFu, dv, j + 2);
            float w3 = __shfl_sync(0xFFFFFFFFu, dv, j + 3);
            float w4 = __shfl_sync(0xFFFFFFFFu, dv, j + 4);
            float w5 = __shfl_sync(0xFFFFFFFFu, dv, j + 5);
            float w6 = __shfl_sync(0xFFFFFFFFu, dv, j + 6);
            float w7 = __shfl_sync(0xFFFFFFFFu, dv, j + 7);
            float4 v0 = loadrow(s0);
            float4 v1 = loadrow(s1);
            float4 v2 = loadrow(s2);
            float4 v3 = loadrow(s3);
            float4 v4 = loadrow(s4);
            float4 v5 = loadrow(s5);
            float4 v6 = loadrow(s6);
            float4 v7 = loadrow(s7);
            acc.x = fmaf(w0, v0.x, fmaf(w1, v1.x, fmaf(w2, v2.x, fmaf(w3, v3.x,
                    fmaf(w4, v4.x, fmaf(w5, v5.x, fmaf(w6, v6.x, fmaf(w7, v7.x, acc.x))))))));
            acc.y = fmaf(w0, v0.y, fmaf(w1, v1.y, fmaf(w2, v2.y, fmaf(w3, v3.y,
                    fmaf(w4, v4.y, fmaf(w5, v5.y, fmaf(w6, v6.y, fmaf(w7, v7.y, acc.y))))))));
            acc.z = fmaf(w0, v0.z, fmaf(w1, v1.z, fmaf(w2, v2.z, fmaf(w3, v3.z,
                    fmaf(w4, v4.z, fmaf(w5, v5.z, fmaf(w6, v6.z, fmaf(w7, v7.z, acc.z))))))));
            acc.w = fmaf(w0, v0.w, fmaf(w1, v1.w, fmaf(w2, v2.w, fmaf(w3, v3.w,
                    fmaf(w4, v4.w, fmaf(w5, v5.w, fmaf(w6, v6.w, fmaf(w7, v7.w, acc.w))))))));
        }
        for (; j < m; j++) {
            int s = __shfl_sync(0xFFFFFFFFu, idx, j);
            float ws = __shfl_sync(0xFFFFFFFFu, dv, j);
            float4 v = loadrow(s);
            acc.x = fmaf(ws, v.x, acc.x);
            acc.y = fmaf(ws, v.y, acc.y);
            acc.z = fmaf(ws, v.z, acc.z);
            acc.w = fmaf(ws, v.w, acc.w);
        }
    }

    float dinv = __ldg(&g_dinv[gw]);
    float4 w  = loadrow(gw);
    float4 bb = *(const float4*)&b[lane * 4];

    float v0 = fmaxf(fmaf(dinv, fmaf(dinv, w.x, acc.x), bb.x), 0.0f);
    float v1 = fmaxf(fmaf(dinv, fmaf(dinv, w.y, acc.y), bb.y), 0.0f);
    float v2 = fmaxf(fmaf(dinv, fmaf(dinv, w.z, acc.z), bb.z), 0.0f);
    float v3 = fmaxf(fmaf(dinv, fmaf(dinv, w.w, acc.w), bb.w), 0.0f);

    float m = fmaxf(fmaxf(v0, v1), fmaxf(v2, v3));
    #pragma unroll
    for (int off = 16; off > 0; off >>= 1)
        m = fmaxf(m, __shfl_xor_sync(0xFFFFFFFFu, m, off));

    float e0 = __expf(v0 - m);
    float e1 = __expf(v1 - m);
    float e2 = __expf(v2 - m);
    float e3 = __expf(v3 - m);
    float s = e0 + e1 + e2 + e3;
    #pragma unroll
    for (int off = 16; off > 0; off >>= 1)
        s += __shfl_xor_sync(0xFFFFFFFFu, s, off);

    float inv = __frcp_rn(s);
    float4 o;
    o.x = e0 * inv; o.y = e1 * inv; o.z = e2 * inv; o.w = e3 * inv;
    *(float4*)&out[(size_t)gw * LDIM + lane * 4] = o;
}

// ---------------------------------------------------------------------------
extern "C" void kernel_launch(void* const* d_in, const int* in_sizes, int n_in,
                              void* d_out, int out_size)
{
    const float* x  = (const float*)d_in[0];
    const int*   ei = (const int*)d_in[1];
    const float* W  = (const float*)d_in[2];
    const float* b  = (const float*)d_in[3];
    float* out = (float*)d_out;

    int N = in_sizes[0] / LDIM;   // 50000
    int E = in_sizes[1] / 2;      // 800000
    const int* src = ei;
    const int* dst = ei + E;
    int nchunk = (N + SCAN_BLK - 1) / SCAN_BLK;

    cudaStream_t s2;
    cudaStreamCreateWithFlags(&s2, cudaStreamNonBlocking);
    cudaEvent_t evRoot, evGemm;
    cudaEventCreateWithFlags(&evRoot, cudaEventDisableTiming);
    cudaEventCreateWithFlags(&evGemm, cudaEventDisableTiming);

    cudaEventRecord(evRoot, 0);
    cudaStreamWaitEvent(s2, evRoot, 0);

    // side stream: W split + GEMM
    wsplit_kernel<<<(64 * LDIM + 255) / 256, 256, 0, s2>>>(W);
    cudaFuncSetAttribute(gemm_mma_kernel,
                         cudaFuncAttributeMaxDynamicSharedMemorySize, GEMM_SMEM);
    gemm_mma_kernel<<<(N + 127) / 128, 512, GEMM_SMEM, s2>>>(x, N);
    cudaEventRecord(evGemm, s2);

    // main stream: CSR build
    zero_kernel<<<(N + 255) / 256, 256>>>(N, nchunk);
    hist_kernel<<<(E + 255) / 256, 256>>>(dst, E);
    scan_lookback_kernel<<<nchunk, SCAN_BLK>>>(N);
    fill_kernel<<<(E + 255) / 256, 256>>>(src, dst, E);

    cudaStreamWaitEvent(0, evGemm, 0);
    long long gthreads = (long long)N * 32;
    gather_finalize_kernel<<<(int)((gthreads + 255) / 256), 256>>>(b, out, N);
}

// round 15
// speedup vs baseline: 2.6629x; 1.0208x over previous
#include <cuda_runtime.h>
#include <cuda_fp16.h>

#define LDIM 128
#define NMAX 50000
#define EMAX 800000
#define SCAN_BLK 1024
#define NCHUNK_MAX ((NMAX + SCAN_BLK - 1) / SCAN_BLK)

// Scratch (allocation-free rule: __device__ globals)
__device__ __align__(16) __half2 g_xwh[(size_t)NMAX * 64]; // x@W as fp16 pairs
__device__ float g_dinv[NMAX];
__device__ int g_cnt[NMAX];
__device__ int g_off[NMAX];
__device__ int g_cur[NMAX];
__device__ int g_adj[EMAX];
__device__ volatile int g_look[NCHUNK_MAX];
__device__ unsigned g_wbhi[64 * LDIM];  // W bf16 hi, packed k-pairs [kpair][n]
__device__ unsigned g_wblo[64 * LDIM];  // W bf16 lo residuals

// ---- bf16 pack/split helpers ------------------------------------------------
__device__ __forceinline__ unsigned packbf(float x, float y) {
    unsigned r;
    asm("cvt.rn.bf16x2.f32 %0, %1, %2;" : "=r"(r) : "f"(y), "f"(x));
    return r;
}
__device__ __forceinline__ float bf_lo(unsigned r) { return __uint_as_float(r << 16); }
__device__ __forceinline__ float bf_hi(unsigned r) { return __uint_as_float(r & 0xFFFF0000u); }
__device__ __forceinline__ void split_bf(float x, float y, unsigned& hi, unsigned& lo) {
    hi = packbf(x, y);
    lo = packbf(x - bf_lo(hi), y - bf_hi(hi));
}

// ---------------------------------------------------------------------------
// K0: zero counters + lookback words
// ---------------------------------------------------------------------------
__global__ void zero_kernel(int N, int nchunk) {
    int i = blockIdx.x * blockDim.x + threadIdx.x;
    if (i < N) g_cnt[i] = 0;
    if (i < nchunk) g_look[i] = 0;
}

// ---------------------------------------------------------------------------
// K1: histogram of dst — int4 vectorized, 4 edges/thread
// ---------------------------------------------------------------------------
__global__ void hist_kernel(const int* __restrict__ dst, int E) {
    int q = blockIdx.x * blockDim.x + threadIdx.x;
    int e = q * 4;
    if (e + 3 < E) {
        int4 d = __ldg((const int4*)(dst + e));
        atomicAdd(&g_cnt[d.x], 1);
        atomicAdd(&g_cnt[d.y], 1);
        atomicAdd(&g_cnt[d.z], 1);
        atomicAdd(&g_cnt[d.w], 1);
    } else {
        for (int i = e; i < E; i++) atomicAdd(&g_cnt[dst[i]], 1);
    }
}

__global__ void wsplit_kernel(const float* __restrict__ W) {
    int i = blockIdx.x * blockDim.x + threadIdx.x;
    if (i < 64 * LDIM) {
        int kp = i >> 7, n = i & 127;
        float v0 = W[(2 * kp) * LDIM + n];
        float v1 = W[(2 * kp + 1) * LDIM + n];
        unsigned hi, lo;
        split_bf(v0, v1, hi, lo);
        g_wbhi[i] = hi;
        g_wblo[i] = lo;
    }
}

// ---------------------------------------------------------------------------
// K2: decoupled-lookback exclusive scan; emits g_dinv and seeds g_cur
// ---------------------------------------------------------------------------
__global__ __launch_bounds__(SCAN_BLK) void scan_lookback_kernel(int N) {
    __shared__ int warpsum[32];
    __shared__ int s_prefix;
    int t = threadIdx.x, lane = t & 31, wid = t >> 5;
    int bid = blockIdx.x;
    int gid = bid * SCAN_BLK + t;
    int v = (gid < N) ? g_cnt[gid] : 0;

    int x = v;
    #pragma unroll
    for (int off = 1; off < 32; off <<= 1) {
        int y = __shfl_up_sync(0xFFFFFFFFu, x, off);
        if (lane >= off) x += y;
    }
    if (lane == 31) warpsum[wid] = x;
    __syncthreads();
    if (wid == 0) {
        int w = warpsum[lane];
        #pragma unroll
        for (int off = 1; off < 32; off <<= 1) {
            int y = __shfl_up_sync(0xFFFFFFFFu, w, off);
            if (lane >= off) w += y;
        }
        warpsum[lane] = w;
    }
    __syncthreads();
    int warp_prefix = (wid == 0) ? 0 : warpsum[wid - 1];
    int block_total = warpsum[31];

    if (t == 0) g_look[bid] = block_total + 1;

    if (wid == 0) {
        int acc = 0;
        for (int base = 0; base < bid; base += 32) {
            int j = base + lane;
            int val = 0;
            if (j < bid) {
                do { val = g_look[j]; } while (val == 0);
                val -= 1;
            }
            #pragma unroll
            for (int off = 16; off > 0; off >>= 1)
                val += __shfl_xor_sync(0xFFFFFFFFu, val, off);
            acc += val;
        }
        if (lane == 0) s_prefix = acc;
    }
    __syncthreads();

    int o = s_prefix + warp_prefix + x - v;
    if (gid < N) {
        g_off[gid] = o;
        g_cur[gid] = o;
        g_dinv[gid] = rsqrtf((float)(v + 1));
    }
}

// ---------------------------------------------------------------------------
// K3: bucket fill — 2 edges/thread for MLP on the ATOMG chain
// ---------------------------------------------------------------------------
__global__ void fill_kernel(const int* __restrict__ src,
                            const int* __restrict__ dst, int E) {
    int q = blockIdx.x * blockDim.x + threadIdx.x;
    int e = q * 2;
    if (e + 1 < E) {
        int2 s = __ldg((const int2*)(src + e));
        int2 d = __ldg((const int2*)(dst + e));
        int p0 = atomicAdd(&g_cur[d.x], 1);
        int p1 = atomicAdd(&g_cur[d.y], 1);
        g_adj[p0] = s.x;
        g_adj[p1] = s.y;
    } else if (e < E) {
        int d = dst[e];
        int pos = atomicAdd(&g_cur[d], 1);
        g_adj[pos] = src[e];
    }
}

// ---------------------------------------------------------------------------
// K4: bf16 m16n8k16 GEMM, 2xBF16 split, cp.async pipe. fp16 output.
// ---------------------------------------------------------------------------
#define AST 36
#define BST 136
#define A_WORDS (128 * AST)
#define B_HI_WORDS (16 * BST)
#define B_BUF_WORDS (2 * B_HI_WORDS)
#define OFF_A(b)  ((b) * A_WORDS)
#define OFF_BH(b) (2 * A_WORDS + (b) * B_BUF_WORDS)
#define OFF_BL(b) (OFF_BH(b) + B_HI_WORDS)
#define GEMM_SMEM ((2 * A_WORDS + 2 * B_BUF_WORDS) * 4)

__device__ __forceinline__ void cp16(unsigned saddr, const void* g, unsigned srcsz) {
    asm volatile("cp.async.ca.shared.global [%0], [%1], 16, %2;"
                 :: "r"(saddr), "l"(g), "r"(srcsz) : "memory");
}

__device__ __forceinline__ void mma_bf16(float* c,
                                         unsigned a0, unsigned a1,
                                         unsigned a2, unsigned a3,
                                         unsigned b0, unsigned b1) {
    asm volatile(
        "mma.sync.aligned.m16n8k16.row.col.f32.bf16.bf16.f32 "
        "{%0,%1,%2,%3}, {%4,%5,%6,%7}, {%8,%9}, {%0,%1,%2,%3};"
        : "+f"(c[0]), "+f"(c[1]), "+f"(c[2]), "+f"(c[3])
        : "r"(a0), "r"(a1), "r"(a2), "r"(a3), "r"(b0), "r"(b1));
}

__global__ __launch_bounds__(512, 2) void gemm_mma_kernel(
    const float* __restrict__ x, int N)
{
    extern __shared__ unsigned smu[];
    float* smf = (float*)smu;
    unsigned sbase = (unsigned)__cvta_generic_to_shared(smu);
    const int tid = threadIdx.x;
    const int wid = tid >> 5;
    const int lane = tid & 31;
    const int g = lane >> 2;
    const int t4 = lane & 3;
    const int block_row = blockIdx.x * 128;
    const int wr0 = (wid >> 1) * 16;
    const int wc0 = (wid & 1) * 64;

    float acc[8][4];
    #pragma unroll
    for (int nt = 0; nt < 8; nt++)
        #pragma unroll
        for (int j = 0; j < 4; j++) acc[nt][j] = 0.0f;

    auto prefetch = [&](int s, int buf) {
        int k0 = s * 32, kp0 = s * 16;
        for (int c = tid; c < 1024; c += 512) {
            int r = c >> 3, cj = c & 7;
            int grow = block_row + r;
            unsigned sa = sbase + (unsigned)(OFF_A(buf) + r * AST + cj * 4) * 4u;
            int crow = grow < N ? grow : (N - 1);
            const float* gp = x + (size_t)crow * LDIM + k0 + cj * 4;
            cp16(sa, gp, grow < N ? 16u : 0u);
        }
        for (int c = tid; c < 1024; c += 512) {
            int half = c >> 9;
            int cc = c & 511;
            int kp = cc >> 5, cj = cc & 31;
            unsigned off = half ? (unsigned)OFF_BL(buf) : (unsigned)OFF_BH(buf);
            unsigned sa = sbase + (off + (unsigned)(kp * BST + cj * 4)) * 4u;
            const unsigned* gp = (half ? g_wblo : g_wbhi) + (kp0 + kp) * LDIM + cj * 4;
            cp16(sa, gp, 16u);
        }
    };

    prefetch(0, 0);
    asm volatile("cp.async.commit_group;" ::: "memory");

    #pragma unroll 1
    for (int s = 0; s < 4; s++) {
        int buf = s & 1;
        if (s < 3) {
            prefetch(s + 1, buf ^ 1);
            asm volatile("cp.async.commit_group;" ::: "memory");
            asm volatile("cp.async.wait_group 1;" ::: "memory");
        } else {
            asm volatile("cp.async.wait_group 0;" ::: "memory");
        }
        __syncthreads();

        #pragma unroll
        for (int ks = 0; ks < 2; ks++) {
            const float2* A2r0 = (const float2*)(smf + OFF_A(buf)) + (wr0 + g) * (AST / 2) + ks * 8;
            const float2* A2r1 = A2r0 + 8 * (AST / 2);
            float2 f0 = A2r0[t4];
            float2 f1 = A2r1[t4];
            float2 f2 = A2r0[t4 + 4];
            float2 f3 = A2r1[t4 + 4];
            unsigned ah0, al0, ah1, al1, ah2, al2, ah3, al3;
            split_bf(f0.x, f0.y, ah0, al0);
            split_bf(f1.x, f1.y, ah1, al1);
            split_bf(f2.x, f2.y, ah2, al2);
            split_bf(f3.x, f3.y, ah3, al3);

            const unsigned* Bh = smu + OFF_BH(buf) + (ks * 8 + t4) * BST + wc0 + g;
            const unsigned* Bl = smu + OFF_BL(buf) + (ks * 8 + t4) * BST + wc0 + g;
            #pragma unroll
            for (int nt = 0; nt < 8; nt++) {
                unsigned bh0 = Bh[nt * 8];
                unsigned bh1 = Bh[4 * BST + nt * 8];
                unsigned bl0 = Bl[nt * 8];
                unsigned bl1 = Bl[4 * BST + nt * 8];
                mma_bf16(acc[nt], ah0, ah1, ah2, ah3, bh0, bh1);
                mma_bf16(acc[nt], ah0, ah1, ah2, ah3, bl0, bl1);
                mma_bf16(acc[nt], al0, al1, al2, al3, bh0, bh1);
            }
        }
        __syncthreads();
    }

    int row0 = block_row + wr0 + g;
    int row1 = row0 + 8;

    #pragma unroll
    for (int nt = 0; nt < 8; nt++) {
        int cp2 = (wc0 >> 1) + nt * 4 + t4;
        if (row0 < N)
            g_xwh[(size_t)row0 * 64 + cp2] = __floats2half2_rn(acc[nt][0], acc[nt][1]);
        if (row1 < N)
            g_xwh[(size_t)row1 * 64 + cp2] = __floats2half2_rn(acc[nt][2], acc[nt][3]);
    }
}

// ---------------------------------------------------------------------------
// K5: gather + finalize; single LDG.64 per row per lane, fp32 accumulate.
// ---------------------------------------------------------------------------
__global__ void gather_finalize_kernel(const float* __restrict__ b,
                                       float* __restrict__ out, int N)
{
    int gw = (blockIdx.x * blockDim.x + threadIdx.x) >> 5;
    int lane = threadIdx.x & 31;
    if (gw >= N) return;

    int start = g_off[gw];
    int len   = g_cnt[gw];

    float4 acc = make_float4(0.f, 0.f, 0.f, 0.f);

    // one 8B load per row per lane (lane's 4 cols = 2 contiguous half2)
    const uint2* xw2 = (const uint2*)g_xwh;   // row = 32 uint2
    auto loadrow = [&](int s) -> float4 {
        uint2 u = __ldg(xw2 + (size_t)s * 32 + lane);
        float2 a = __half22float2(*(const __half2*)&u.x);
        float2 c = __half22float2(*(const __half2*)&u.y);
        return make_float4(a.x, a.y, c.x, c.y);
    };

    for (int base = 0; base < len; base += 32) {
        int idx = 0; float dv = 0.0f;
        if (base + lane < len) {
            idx = __ldg(&g_adj[start + base + lane]);
            dv = __ldg(&g_dinv[idx]);
        }
        int m = min(32, len - base);
        int j = 0;
        for (; j + 8 <= m; j += 8) {
            int s0 = __shfl_sync(0xFFFFFFFFu, idx, j + 0);
            int s1 = __shfl_sync(0xFFFFFFFFu, idx, j + 1);
            int s2 = __shfl_sync(0xFFFFFFFFu, idx, j + 2);
            int s3 = __shfl_sync(0xFFFFFFFFu, idx, j + 3);
            int s4 = __shfl_sync(0xFFFFFFFFu, idx, j + 4);
            int s5 = __shfl_sync(0xFFFFFFFFu, idx, j + 5);
            int s6 = __shfl_sync(0xFFFFFFFFu, idx, j + 6);
            int s7 = __shfl_sync(0xFFFFFFFFu, idx, j + 7);
            float w0 = __shfl_sync(0xFFFFFFFFu, dv, j + 0);
            float w1 = __shfl_sync(0xFFFFFFFFu, dv, j + 1);
            float w2 = __shfl_sync(0xFFFFFFFFu, dv, j + 2);
            float w3 = __shfl_sync(0xFFFFFFFFu, dv, j + 3);
            float w4 = __shfl_sync(0xFFFFFFFFu, dv, j + 4);
            float w5 = __shfl_sync(0xFFFFFFFFu, dv, j + 5);
            float w6 = __shfl_sync(0xFFFFFFFFu, dv, j + 6);
            float w7 = __shfl_sync(0xFFFFFFFFu, dv, j + 7);
            float4 v0 = loadrow(s0);
            float4 v1 = loadrow(s1);
            float4 v2 = loadrow(s2);
            float4 v3 = loadrow(s3);
            float4 v4 = loadrow(s4);
            float4 v5 = loadrow(s5);
            float4 v6 = loadrow(s6);
            float4 v7 = loadrow(s7);
            acc.x = fmaf(w0, v0.x, fmaf(w1, v1.x, fmaf(w2, v2.x, fmaf(w3, v3.x,
                    fmaf(w4, v4.x, fmaf(w5, v5.x, fmaf(w6, v6.x, fmaf(w7, v7.x, acc.x))))))));
            acc.y = fmaf(w0, v0.y, fmaf(w1, v1.y, fmaf(w2, v2.y, fmaf(w3, v3.y,
                    fmaf(w4, v4.y, fmaf(w5, v5.y, fmaf(w6, v6.y, fmaf(w7, v7.y, acc.y))))))));
            acc.z = fmaf(w0, v0.z, fmaf(w1, v1.z, fmaf(w2, v2.z, fmaf(w3, v3.z,
                    fmaf(w4, v4.z, fmaf(w5, v5.z, fmaf(w6, v6.z, fmaf(w7, v7.z, acc.z))))))));
            acc.w = fmaf(w0, v0.w, fmaf(w1, v1.w, fmaf(w2, v2.w, fmaf(w3, v3.w,
                    fmaf(w4, v4.w, fmaf(w5, v5.w, fmaf(w6, v6.w, fmaf(w7, v7.w, acc.w))))))));
        }
        for (; j < m; j++) {
            int s = __shfl_sync(0xFFFFFFFFu, idx, j);
            float ws = __shfl_sync(0xFFFFFFFFu, dv, j);
            float4 v = loadrow(s);
            acc.x = fmaf(ws, v.x, acc.x);
            acc.y = fmaf(ws, v.y, acc.y);
            acc.z = fmaf(ws, v.z, acc.z);
            acc.w = fmaf(ws, v.w, acc.w);
        }
    }

    float dinv = __ldg(&g_dinv[gw]);
    float4 w  = loadrow(gw);
    float4 bb = *(const float4*)&b[lane * 4];

    float v0 = fmaxf(fmaf(dinv, fmaf(dinv, w.x, acc.x), bb.x), 0.0f);
    float v1 = fmaxf(fmaf(dinv, fmaf(dinv, w.y, acc.y), bb.y), 0.0f);
    float v2 = fmaxf(fmaf(dinv, fmaf(dinv, w.z, acc.z), bb.z), 0.0f);
    float v3 = fmaxf(fmaf(dinv, fmaf(dinv, w.w, acc.w), bb.w), 0.0f);

    float m = fmaxf(fmaxf(v0, v1), fmaxf(v2, v3));
    #pragma unroll
    for (int off = 16; off > 0; off >>= 1)
        m = fmaxf(m, __shfl_xor_sync(0xFFFFFFFFu, m, off));

    float e0 = __expf(v0 - m);
    float e1 = __expf(v1 - m);
    float e2 = __expf(v2 - m);
    float e3 = __expf(v3 - m);
    float s = e0 + e1 + e2 + e3;
    #pragma unroll
    for (int off = 16; off > 0; off >>= 1)
        s += __shfl_xor_sync(0xFFFFFFFFu, s, off);

    float inv = __frcp_rn(s);
    float4 o;
    o.x = e0 * inv; o.y = e1 * inv; o.z = e2 * inv; o.w = e3 * inv;
    *(float4*)&out[(size_t)gw * LDIM + lane * 4] = o;
}

// ---------------------------------------------------------------------------
extern "C" void kernel_launch(void* const* d_in, const int* in_sizes, int n_in,
                              void* d_out, int out_size)
{
    const float* x  = (const float*)d_in[0];
    const int*   ei = (const int*)d_in[1];
    const float* W  = (const float*)d_in[2];
    const float* b  = (const float*)d_in[3];
    float* out = (float*)d_out;

    int N = in_sizes[0] / LDIM;   // 50000
    int E = in_sizes[1] / 2;      // 800000
    const int* src = ei;
    const int* dst = ei + E;
    int nchunk = (N + SCAN_BLK - 1) / SCAN_BLK;

    cudaStream_t s2;
    cudaStreamCreateWithFlags(&s2, cudaStreamNonBlocking);
    cudaEvent_t evRoot, evGemm;
    cudaEventCreateWithFlags(&evRoot, cudaEventDisableTiming);
    cudaEventCreateWithFlags(&evGemm, cudaEventDisableTiming);

    cudaEventRecord(evRoot, 0);
    cudaStreamWaitEvent(s2, evRoot, 0);

    // side stream: W split + GEMM
    wsplit_kernel<<<(64 * LDIM + 255) / 256, 256, 0, s2>>>(W);
    cudaFuncSetAttribute(gemm_mma_kernel,
                         cudaFuncAttributeMaxDynamicSharedMemorySize, GEMM_SMEM);
    gemm_mma_kernel<<<(N + 127) / 128, 512, GEMM_SMEM, s2>>>(x, N);
    cudaEventRecord(evGemm, s2);

    // main stream: CSR build
    zero_kernel<<<(N + 255) / 256, 256>>>(N, nchunk);
    {
        int q = (E + 3) / 4;
        hist_kernel<<<(q + 255) / 256, 256>>>(dst, E);
    }
    scan_lookback_kernel<<<nchunk, SCAN_BLK>>>(N);
    {
        int q = (E + 1) / 2;
        fill_kernel<<<(q + 255) / 256, 256>>>(src, dst, E);
    }

    cudaStreamWaitEvent(0, evGemm, 0);
    long long gthreads = (long long)N * 32;
    gather_finalize_kernel<<<(int)((gthreads + 255) / 256), 256>>>(b, out, N);
}

// round 17
// speedup vs baseline: 2.8062x; 1.0538x over previous
#include <cuda_runtime.h>
#include <cuda_fp16.h>

#define LDIM 128
#define NMAX 50000
#define EMAX 800000
#define SCAN_BLK 1024
#define NCHUNK_MAX ((NMAX + SCAN_BLK - 1) / SCAN_BLK)

// Scratch (allocation-free rule: __device__ globals)
__device__ __align__(16) __half2 g_xwh[(size_t)NMAX * 64]; // x@W fp16; prescaled by dinv
__device__ float g_dinv[NMAX];
__device__ int g_cnt[NMAX];
__device__ int g_off[NMAX];
__device__ int g_cur[NMAX];
__device__ int g_adj[EMAX];
__device__ volatile int g_look[NCHUNK_MAX];
__device__ unsigned g_wbhi[64 * LDIM];
__device__ unsigned g_wblo[64 * LDIM];

// ---- bf16 pack/split helpers ------------------------------------------------
__device__ __forceinline__ unsigned packbf(float x, float y) {
    unsigned r;
    asm("cvt.rn.bf16x2.f32 %0, %1, %2;" : "=r"(r) : "f"(y), "f"(x));
    return r;
}
__device__ __forceinline__ float bf_lo(unsigned r) { return __uint_as_float(r << 16); }
__device__ __forceinline__ float bf_hi(unsigned r) { return __uint_as_float(r & 0xFFFF0000u); }
__device__ __forceinline__ void split_bf(float x, float y, unsigned& hi, unsigned& lo) {
    hi = packbf(x, y);
    lo = packbf(x - bf_lo(hi), y - bf_hi(hi));
}

// ---------------------------------------------------------------------------
__global__ void zero_kernel(int N, int nchunk) {
    int i = blockIdx.x * blockDim.x + threadIdx.x;
    if (i < N) g_cnt[i] = 0;
    if (i < nchunk) g_look[i] = 0;
}

__global__ void hist_kernel(const int* __restrict__ dst, int E) {
    int q = blockIdx.x * blockDim.x + threadIdx.x;
    int e = q * 4;
    if (e + 3 < E) {
        int4 d = __ldg((const int4*)(dst + e));
        atomicAdd(&g_cnt[d.x], 1);
        atomicAdd(&g_cnt[d.y], 1);
        atomicAdd(&g_cnt[d.z], 1);
        atomicAdd(&g_cnt[d.w], 1);
    } else {
        for (int i = e; i < E; i++) atomicAdd(&g_cnt[dst[i]], 1);
    }
}

__global__ void wsplit_kernel(const float* __restrict__ W) {
    int i = blockIdx.x * blockDim.x + threadIdx.x;
    if (i < 64 * LDIM) {
        int kp = i >> 7, n = i & 127;
        float v0 = W[(2 * kp) * LDIM + n];
        float v1 = W[(2 * kp + 1) * LDIM + n];
        unsigned hi, lo;
        split_bf(v0, v1, hi, lo);
        g_wbhi[i] = hi;
        g_wblo[i] = lo;
    }
}

__global__ __launch_bounds__(SCAN_BLK) void scan_lookback_kernel(int N) {
    __shared__ int warpsum[32];
    __shared__ int s_prefix;
    int t = threadIdx.x, lane = t & 31, wid = t >> 5;
    int bid = blockIdx.x;
    int gid = bid * SCAN_BLK + t;
    int v = (gid < N) ? g_cnt[gid] : 0;

    int x = v;
    #pragma unroll
    for (int off = 1; off < 32; off <<= 1) {
        int y = __shfl_up_sync(0xFFFFFFFFu, x, off);
        if (lane >= off) x += y;
    }
    if (lane == 31) warpsum[wid] = x;
    __syncthreads();
    if (wid == 0) {
        int w = warpsum[lane];
        #pragma unroll
        for (int off = 1; off < 32; off <<= 1) {
            int y = __shfl_up_sync(0xFFFFFFFFu, w, off);
            if (lane >= off) w += y;
        }
        warpsum[lane] = w;
    }
    __syncthreads();
    int warp_prefix = (wid == 0) ? 0 : warpsum[wid - 1];
    int block_total = warpsum[31];

    if (t == 0) g_look[bid] = block_total + 1;

    if (wid == 0) {
        int acc = 0;
        for (int base = 0; base < bid; base += 32) {
            int j = base + lane;
            int val = 0;
            if (j < bid) {
                do { val = g_look[j]; } while (val == 0);
                val -= 1;
            }
            #pragma unroll
            for (int off = 16; off > 0; off >>= 1)
                val += __shfl_xor_sync(0xFFFFFFFFu, val, off);
            acc += val;
        }
        if (lane == 0) s_prefix = acc;
    }
    __syncthreads();

    int o = s_prefix + warp_prefix + x - v;
    if (gid < N) {
        g_off[gid] = o;
        g_cur[gid] = o;
        g_dinv[gid] = rsqrtf((float)(v + 1));
    }
}

__global__ void fill_kernel(const int* __restrict__ src,
                            const int* __restrict__ dst, int E) {
    int q = blockIdx.x * blockDim.x + threadIdx.x;
    int e = q * 2;
    if (e + 1 < E) {
        int2 s = __ldg((const int2*)(src + e));
        int2 d = __ldg((const int2*)(dst + e));
        int p0 = atomicAdd(&g_cur[d.x], 1);
        int p1 = atomicAdd(&g_cur[d.y], 1);
        g_adj[p0] = s.x;
        g_adj[p1] = s.y;
    } else if (e < E) {
        int d = dst[e];
        int pos = atomicAdd(&g_cur[d], 1);
        g_adj[pos] = src[e];
    }
}

// ---------------------------------------------------------------------------
// K4: bf16 m16n8k16 GEMM, 2xBF16 split, cp.async pipe. fp16 output (unscaled).
// ---------------------------------------------------------------------------
#define AST 36
#define BST 136
#define A_WORDS (128 * AST)
#define B_HI_WORDS (16 * BST)
#define B_BUF_WORDS (2 * B_HI_WORDS)
#define OFF_A(b)  ((b) * A_WORDS)
#define OFF_BH(b) (2 * A_WORDS + (b) * B_BUF_WORDS)
#define OFF_BL(b) (OFF_BH(b) + B_HI_WORDS)
#define GEMM_SMEM ((2 * A_WORDS + 2 * B_BUF_WORDS) * 4)

__device__ __forceinline__ void cp16(unsigned saddr, const void* g, unsigned srcsz) {
    asm volatile("cp.async.ca.shared.global [%0], [%1], 16, %2;"
                 :: "r"(saddr), "l"(g), "r"(srcsz) : "memory");
}

__device__ __forceinline__ void mma_bf16(float* c,
                                         unsigned a0, unsigned a1,
                                         unsigned a2, unsigned a3,
                                         unsigned b0, unsigned b1) {
    asm volatile(
        "mma.sync.aligned.m16n8k16.row.col.f32.bf16.bf16.f32 "
        "{%0,%1,%2,%3}, {%4,%5,%6,%7}, {%8,%9}, {%0,%1,%2,%3};"
        : "+f"(c[0]), "+f"(c[1]), "+f"(c[2]), "+f"(c[3])
        : "r"(a0), "r"(a1), "r"(a2), "r"(a3), "r"(b0), "r"(b1));
}

__global__ __launch_bounds__(512, 2) void gemm_mma_kernel(
    const float* __restrict__ x, int N)
{
    extern __shared__ unsigned smu[];
    float* smf = (float*)smu;
    unsigned sbase = (unsigned)__cvta_generic_to_shared(smu);
    const int tid = threadIdx.x;
    const int wid = tid >> 5;
    const int lane = tid & 31;
    const int g = lane >> 2;
    const int t4 = lane & 3;
    const int block_row = blockIdx.x * 128;
    const int wr0 = (wid >> 1) * 16;
    const int wc0 = (wid & 1) * 64;

    float acc[8][4];
    #pragma unroll
    for (int nt = 0; nt < 8; nt++)
        #pragma unroll
        for (int j = 0; j < 4; j++) acc[nt][j] = 0.0f;

    auto prefetch = [&](int s, int buf) {
        int k0 = s * 32, kp0 = s * 16;
        for (int c = tid; c < 1024; c += 512) {
            int r = c >> 3, cj = c & 7;
            int grow = block_row + r;
            unsigned sa = sbase + (unsigned)(OFF_A(buf) + r * AST + cj * 4) * 4u;
            int crow = grow < N ? grow : (N - 1);
            const float* gp = x + (size_t)crow * LDIM + k0 + cj * 4;
            cp16(sa, gp, grow < N ? 16u : 0u);
        }
        for (int c = tid; c < 1024; c += 512) {
            int half = c >> 9;
            int cc = c & 511;
            int kp = cc >> 5, cj = cc & 31;
            unsigned off = half ? (unsigned)OFF_BL(buf) : (unsigned)OFF_BH(buf);
            unsigned sa = sbase + (off + (unsigned)(kp * BST + cj * 4)) * 4u;
            const unsigned* gp = (half ? g_wblo : g_wbhi) + (kp0 + kp) * LDIM + cj * 4;
            cp16(sa, gp, 16u);
        }
    };

    prefetch(0, 0);
    asm volatile("cp.async.commit_group;" ::: "memory");

    #pragma unroll 1
    for (int s = 0; s < 4; s++) {
        int buf = s & 1;
        if (s < 3) {
            prefetch(s + 1, buf ^ 1);
            asm volatile("cp.async.commit_group;" ::: "memory");
            asm volatile("cp.async.wait_group 1;" ::: "memory");
        } else {
            asm volatile("cp.async.wait_group 0;" ::: "memory");
        }
        __syncthreads();

        #pragma unroll
        for (int ks = 0; ks < 2; ks++) {
            const float2* A2r0 = (const float2*)(smf + OFF_A(buf)) + (wr0 + g) * (AST / 2) + ks * 8;
            const float2* A2r1 = A2r0 + 8 * (AST / 2);
            float2 f0 = A2r0[t4];
            float2 f1 = A2r1[t4];
            float2 f2 = A2r0[t4 + 4];
            float2 f3 = A2r1[t4 + 4];
            unsigned ah0, al0, ah1, al1, ah2, al2, ah3, al3;
            split_bf(f0.x, f0.y, ah0, al0);
            split_bf(f1.x, f1.y, ah1, al1);
            split_bf(f2.x, f2.y, ah2, al2);
            split_bf(f3.x, f3.y, ah3, al3);

            const unsigned* Bh = smu + OFF_BH(buf) + (ks * 8 + t4) * BST + wc0 + g;
            const unsigned* Bl = smu + OFF_BL(buf) + (ks * 8 + t4) * BST + wc0 + g;
            #pragma unroll
            for (int nt = 0; nt < 8; nt++) {
                unsigned bh0 = Bh[nt * 8];
                unsigned bh1 = Bh[4 * BST + nt * 8];
                unsigned bl0 = Bl[nt * 8];
                unsigned bl1 = Bl[4 * BST + nt * 8];
                mma_bf16(acc[nt], ah0, ah1, ah2, ah3, bh0, bh1);
                mma_bf16(acc[nt], ah0, ah1, ah2, ah3, bl0, bl1);
                mma_bf16(acc[nt], al0, al1, al2, al3, bh0, bh1);
            }
        }
        __syncthreads();
    }

    int row0 = block_row + wr0 + g;
    int row1 = row0 + 8;

    #pragma unroll
    for (int nt = 0; nt < 8; nt++) {
        int cp2 = (wc0 >> 1) + nt * 4 + t4;
        if (row0 < N)
            g_xwh[(size_t)row0 * 64 + cp2] = __floats2half2_rn(acc[nt][0], acc[nt][1]);
        if (row1 < N)
            g_xwh[(size_t)row1 * 64 + cp2] = __floats2half2_rn(acc[nt][2], acc[nt][3]);
    }
}

// ---------------------------------------------------------------------------
// K4b: prescale rows by dinv[row]
// ---------------------------------------------------------------------------
__global__ void prescale_kernel(int N) {
    int i = blockIdx.x * blockDim.x + threadIdx.x;   // uint4 index (16 per row)
    int total = N * 16;
    if (i >= total) return;
    int row = i >> 4;
    float dv = __ldg(&g_dinv[row]);
    uint4 u = ((const uint4*)g_xwh)[i];
    __half2* h = (__half2*)&u;
    #pragma unroll
    for (int k = 0; k < 4; k++) {
        float2 f = __half22float2(h[k]);
        h[k] = __floats2half2_rn(f.x * dv, f.y * dv);
    }
    ((uint4*)g_xwh)[i] = u;
}

// ---------------------------------------------------------------------------
// K5: gather + finalize; 2 nodes/warp (16 lanes each), LDG.128 rows,
// prescaled features. ALL shuffles use the half-warp segment mask.
// ---------------------------------------------------------------------------
__global__ void gather_finalize_kernel(const float* __restrict__ b,
                                       float* __restrict__ out, int N)
{
    int hw = (blockIdx.x * blockDim.x + threadIdx.x) >> 4;   // node index
    int lane = threadIdx.x & 15;
    const unsigned smask = 0xFFFFu << (threadIdx.x & 16);    // segment mask
    if (hw >= N) return;

    int start = g_off[hw];
    int len   = g_cnt[hw];

    float acc[8];
    #pragma unroll
    for (int k = 0; k < 8; k++) acc[k] = 0.0f;

    const uint4* xw4 = (const uint4*)g_xwh;   // row = 16 uint4 (256B)
    auto addrow = [&](uint4 u) {
        const __half2* h = (const __half2*)&u;
        #pragma unroll
        for (int k = 0; k < 4; k++) {
            float2 f = __half22float2(h[k]);
            acc[2 * k]     += f.x;
            acc[2 * k + 1] += f.y;
        }
    };

    for (int base = 0; base < len; base += 16) {
        int idx = 0;
        if (base + lane < len) idx = __ldg(&g_adj[start + base + lane]);
        int m = min(16, len - base);
        int j = 0;
        for (; j + 4 <= m; j += 4) {
            int s0 = __shfl_sync(smask, idx, j + 0, 16);
            int s1 = __shfl_sync(smask, idx, j + 1, 16);
            int s2 = __shfl_sync(smask, idx, j + 2, 16);
            int s3 = __shfl_sync(smask, idx, j + 3, 16);
            uint4 v0 = __ldg(xw4 + (size_t)s0 * 16 + lane);
            uint4 v1 = __ldg(xw4 + (size_t)s1 * 16 + lane);
            uint4 v2 = __ldg(xw4 + (size_t)s2 * 16 + lane);
            uint4 v3 = __ldg(xw4 + (size_t)s3 * 16 + lane);
            addrow(v0); addrow(v1); addrow(v2); addrow(v3);
        }
        for (; j < m; j++) {
            int s = __shfl_sync(smask, idx, j, 16);
            addrow(__ldg(xw4 + (size_t)s * 16 + lane));
        }
    }

    // self loop: + p_d
    addrow(__ldg(xw4 + (size_t)hw * 16 + lane));

    float dinv = __ldg(&g_dinv[hw]);
    float4 bb0 = *(const float4*)&b[lane * 8];
    float4 bb1 = *(const float4*)&b[lane * 8 + 4];

    float v[8];
    #pragma unroll
    for (int k = 0; k < 4; k++) v[k] = fmaxf(fmaf(dinv, acc[k], ((const float*)&bb0)[k]), 0.0f);
    #pragma unroll
    for (int k = 0; k < 4; k++) v[4 + k] = fmaxf(fmaf(dinv, acc[4 + k], ((const float*)&bb1)[k]), 0.0f);

    float m = v[0];
    #pragma unroll
    for (int k = 1; k < 8; k++) m = fmaxf(m, v[k]);
    #pragma unroll
    for (int off = 8; off > 0; off >>= 1)
        m = fmaxf(m, __shfl_xor_sync(smask, m, off, 16));

    float e[8], s = 0.0f;
    #pragma unroll
    for (int k = 0; k < 8; k++) { e[k] = __expf(v[k] - m); s += e[k]; }
    #pragma unroll
    for (int off = 8; off > 0; off >>= 1)
        s += __shfl_xor_sync(smask, s, off, 16);

    float inv = __frcp_rn(s);
    float4 o0, o1;
    o0.x = e[0] * inv; o0.y = e[1] * inv; o0.z = e[2] * inv; o0.w = e[3] * inv;
    o1.x = e[4] * inv; o1.y = e[5] * inv; o1.z = e[6] * inv; o1.w = e[7] * inv;
    float* op = &out[(size_t)hw * LDIM + lane * 8];
    *(float4*)op = o0;
    *(float4*)(op + 4) = o1;
}

// ---------------------------------------------------------------------------
extern "C" void kernel_launch(void* const* d_in, const int* in_sizes, int n_in,
                              void* d_out, int out_size)
{
    const float* x  = (const float*)d_in[0];
    const int*   ei = (const int*)d_in[1];
    const float* W  = (const float*)d_in[2];
    const float* b  = (const float*)d_in[3];
    float* out = (float*)d_out;

    int N = in_sizes[0] / LDIM;   // 50000
    int E = in_sizes[1] / 2;      // 800000
    const int* src = ei;
    const int* dst = ei + E;
    int nchunk = (N + SCAN_BLK - 1) / SCAN_BLK;

    cudaStream_t s2;
    cudaStreamCreateWithFlags(&s2, cudaStreamNonBlocking);
    cudaEvent_t evRoot, evGemm;
    cudaEventCreateWithFlags(&evRoot, cudaEventDisableTiming);
    cudaEventCreateWithFlags(&evGemm, cudaEventDisableTiming);

    cudaEventRecord(evRoot, 0);
    cudaStreamWaitEvent(s2, evRoot, 0);

    // main stream: CSR build
    zero_kernel<<<(N + 255) / 256, 256>>>(N, nchunk);
    {
        int q = (E + 3) / 4;
        hist_kernel<<<(q + 255) / 256, 256>>>(dst, E);
    }
    scan_lookback_kernel<<<nchunk, SCAN_BLK>>>(N);
    {
        int q = (E + 1) / 2;
        fill_kernel<<<(q + 255) / 256, 256>>>(src, dst, E);
    }

    // side stream: W split + GEMM (independent of edges)
    wsplit_kernel<<<(64 * LDIM + 255) / 256, 256, 0, s2>>>(W);
    cudaFuncSetAttribute(gemm_mma_kernel,
                         cudaFuncAttributeMaxDynamicSharedMemorySize, GEMM_SMEM);
    gemm_mma_kernel<<<(N + 127) / 128, 512, GEMM_SMEM, s2>>>(x, N);
    cudaEventRecord(evGemm, s2);

    // join: prescale needs dinv (main) + xwh (side), then gather
    cudaStreamWaitEvent(0, evGemm, 0);
    {
        int total = N * 16;
        prescale_kernel<<<(total + 255) / 256, 256>>>(N);
    }
    long long gthreads = (long long)N * 16;
    gather_finalize_kernel<<<(int)((gthreads + 255) / 256), 256>>>(b, out, N);
}